// round 5
// baseline (speedup 1.0000x reference)
#include <cuda_runtime.h>
#include <math.h>

// ---------------- static scratch (no allocations allowed) ----------------
#define NMAX 50000
#define EMAX 500000
__device__ float g_xw1[(size_t)NMAX * 8 * 128];  // layer1 per-relation transforms
__device__ float g_xw2[(size_t)NMAX * 8 * 64];   // layer2 per-relation transforms
__device__ float g_h  [(size_t)NMAX * 128];      // layer1 output (root + agg)
__device__ int   g_cnt[NMAX * 8];                // per (dst, rel) edge counts
__device__ float g_inv[NMAX * 8];                // 1 / max(cnt, 1)
__device__ int   g_deg[NMAX];                    // per-dst total degree
__device__ int   g_off[NMAX];                    // CSR offsets (order-free)
__device__ int   g_cur[NMAX];                    // fill cursors
__device__ int   g_epack[EMAX];                  // packed edge record: src*8 + etype
__device__ int   g_total;                        // global slot cursor
__device__ int   g_idx64;                        // 1 if edge buffers are int64

// ---------------- index dtype handling ----------------
// Indices are < 50000 and non-negative. If the buffer is really int64 (LE),
// every odd 32-bit word is 0. If it's int32, odd words are index values
// (nonzero with overwhelming probability over 256 samples).
__global__ void detect_kernel(const int* __restrict__ ei32) {
    __shared__ int any;
    if (threadIdx.x == 0) any = 0;
    __syncthreads();
    int v = ei32[2 * threadIdx.x + 1];
    if (v != 0) atomicOr(&any, 1);
    __syncthreads();
    if (threadIdx.x == 0) g_idx64 = (any == 0) ? 1 : 0;
}

__device__ __forceinline__ int load_idx(const void* p, long long i) {
    if (g_idx64) return (int)((const long long*)p)[i];
    return ((const int*)p)[i];
}

// ---------------- CSR build kernels ----------------
__global__ void zero_kernel(int n8, int E) {
    int i = blockIdx.x * blockDim.x + threadIdx.x;
    if (i < n8) g_cnt[i] = 0;
    if (i < E)  g_epack[i] = 0;
    if (i == 0) g_total = 0;
}

__global__ void count_kernel(const void* __restrict__ ei,
                             const void* __restrict__ et, int E) {
    int e = blockIdx.x * blockDim.x + threadIdx.x;
    if (e < E) {
        int dst = load_idx(ei, (long long)E + e);
        int r   = load_idx(et, e);
        if ((unsigned)dst < (unsigned)NMAX && (unsigned)r < 8u)
            atomicAdd(&g_cnt[dst * 8 + r], 1);
    }
}

// per-node: inv weights per relation, degree, and order-free CSR slot grab
__global__ void inv_deg_kernel(int N) {
    int i = blockIdx.x * blockDim.x + threadIdx.x;
    if (i >= N) return;
    int deg = 0;
    #pragma unroll
    for (int r = 0; r < 8; r++) {
        int c = g_cnt[i * 8 + r];
        g_inv[i * 8 + r] = 1.0f / (float)(c > 0 ? c : 1);
        deg += c;
    }
    g_deg[i] = deg;
    int off = atomicAdd(&g_total, deg);  // per-node contiguity is all we need
    g_off[i] = off;
    g_cur[i] = off;
}

__global__ void fill_kernel(const void* __restrict__ ei,
                            const void* __restrict__ et, int E) {
    int e = blockIdx.x * blockDim.x + threadIdx.x;
    if (e < E) {
        int src = load_idx(ei, e);
        int dst = load_idx(ei, (long long)E + e);
        int r   = load_idx(et, e);
        if ((unsigned)src < (unsigned)NMAX && (unsigned)dst < (unsigned)NMAX &&
            (unsigned)r < 8u) {
            int pos = atomicAdd(&g_cur[dst], 1);
            g_epack[pos] = src * 8 + r;
        }
    }
}

__global__ void sigmoid_kernel(float* __restrict__ out, int n) {
    int i = blockIdx.x * blockDim.x + threadIdx.x;
    if (i < n) out[i] = 1.0f / (1.0f + expf(-out[i]));
}

// ---------------- batched GEMM ----------------
// Per block (blockIdx.y = r): r<8:  xw[m, r, :] = A[m,:] @ W[r]
//                             r==8: outr[m,:]   = A[m,:] @ root + bias
// BM=128, BN=FOUT, K=128 staged in 4 chunks of 32. 8x8 micro-tile per thread.
template <int FOUT, int LAYER>
__global__ void __launch_bounds__(16 * (FOUT / 8))
rgcn_gemm(const float* __restrict__ Aext,
          const float* __restrict__ W,     // [8, 128, FOUT]
          const float* __restrict__ root,  // [128, FOUT]
          const float* __restrict__ bias,  // [FOUT]
          float* __restrict__ outExt,
          int M) {
    constexpr int TX = FOUT / 8;       // 16 or 8
    constexpr int THREADS = 16 * TX;   // 256 or 128
    constexpr int PADM = 132;
    constexpr bool RELU_A = (LAYER == 2);

    __shared__ float As[32 * PADM];    // k-major transposed A slice
    __shared__ float Bs[32 * FOUT];    // W slice, natural layout

    const float* A    = (LAYER == 1) ? Aext : (const float*)g_h;
    float*       xw   = (LAYER == 1) ? g_xw1 : g_xw2;
    float*       outr = (LAYER == 1) ? g_h : outExt;

    const int tid = threadIdx.x;
    const int tx = tid % TX;
    const int ty = tid / TX;
    const int m0 = blockIdx.x * 128;
    const int r  = blockIdx.y;  // 0..7 relations, 8 = root

    const float* Wp = (r < 8) ? (W + (size_t)r * 128 * FOUT) : root;
    const float4* A4 = (const float4*)A;
    const float4* W4 = (const float4*)Wp;
    float4* Bs4 = (float4*)Bs;

    float acc[8][8];
    #pragma unroll
    for (int i = 0; i < 8; i++)
        #pragma unroll
        for (int j = 0; j < 8; j++) acc[i][j] = 0.f;

    #pragma unroll 1
    for (int s = 0; s < 4; s++) {
        #pragma unroll
        for (int i = tid; i < 128 * 8; i += THREADS) {
            int m = i >> 3, kq = i & 7;
            float4 v = make_float4(0.f, 0.f, 0.f, 0.f);
            if (m0 + m < M) v = A4[(size_t)(m0 + m) * 32 + s * 8 + kq];
            if (RELU_A) {
                v.x = fmaxf(v.x, 0.f); v.y = fmaxf(v.y, 0.f);
                v.z = fmaxf(v.z, 0.f); v.w = fmaxf(v.w, 0.f);
            }
            int kb = kq * 4;
            As[(kb + 0) * PADM + m] = v.x;
            As[(kb + 1) * PADM + m] = v.y;
            As[(kb + 2) * PADM + m] = v.z;
            As[(kb + 3) * PADM + m] = v.w;
        }
        #pragma unroll
        for (int i = tid; i < 32 * FOUT / 4; i += THREADS)
            Bs4[i] = W4[s * (32 * FOUT / 4) + i];
        __syncthreads();

        #pragma unroll
        for (int k = 0; k < 32; k++) {
            float4 a0 = *(const float4*)&As[k * PADM + ty * 8];
            float4 a1 = *(const float4*)&As[k * PADM + ty * 8 + 4];
            float4 b0 = *(const float4*)&Bs[k * FOUT + tx * 8];
            float4 b1 = *(const float4*)&Bs[k * FOUT + tx * 8 + 4];
            float a[8] = {a0.x, a0.y, a0.z, a0.w, a1.x, a1.y, a1.z, a1.w};
            float b[8] = {b0.x, b0.y, b0.z, b0.w, b1.x, b1.y, b1.z, b1.w};
            #pragma unroll
            for (int i = 0; i < 8; i++)
                #pragma unroll
                for (int j = 0; j < 8; j++)
                    acc[i][j] = fmaf(a[i], b[j], acc[i][j]);
        }
        __syncthreads();
    }

    float bb[8];
    if (r == 8) {
        #pragma unroll
        for (int j = 0; j < 8; j++) bb[j] = bias[tx * 8 + j];
        #pragma unroll
        for (int i = 0; i < 8; i++)
            #pragma unroll
            for (int j = 0; j < 8; j++) acc[i][j] += bb[j];
    }
    #pragma unroll
    for (int i = 0; i < 8; i++) {
        int m = m0 + ty * 8 + i;
        if (m >= M) break;
        float* d = (r < 8) ? &xw[((size_t)m * 8 + r) * FOUT + tx * 8]
                           : &outr[(size_t)m * FOUT + tx * 8];
        ((float4*)d)[0] = make_float4(acc[i][0], acc[i][1], acc[i][2], acc[i][3]);
        ((float4*)d)[1] = make_float4(acc[i][4], acc[i][5], acc[i][6], acc[i][7]);
    }
}

// ---------------- CSR gather: out[dst] += sum_e xw[epack_e] * inv[dst*8+r_e] ----
// One warp per dst node; exclusive row ownership — no atomics.
template <int FOUT, int LAYER>
__global__ void __launch_bounds__(256)
gather_kernel(float* __restrict__ outExt, int N) {
    const float* xw = (LAYER == 1) ? g_xw1 : g_xw2;
    float* out = (LAYER == 1) ? g_h : outExt;

    int warp = (blockIdx.x * 256 + threadIdx.x) >> 5;
    int lane = threadIdx.x & 31;
    if (warp >= N) return;
    int dst = warp;

    int beg = g_off[dst];
    int end = beg + g_deg[dst];

    if (FOUT == 128) {
        float4 acc = make_float4(0.f, 0.f, 0.f, 0.f);
        int p = (beg < end) ? g_epack[beg] : 0;
        for (int j = beg; j < end; j++) {
            int pn = (j + 1 < end) ? g_epack[j + 1] : 0;
            float w = g_inv[(dst << 3) + (p & 7)];
            float4 v = ((const float4*)(xw + (size_t)p * 128))[lane];
            acc.x = fmaf(v.x, w, acc.x);
            acc.y = fmaf(v.y, w, acc.y);
            acc.z = fmaf(v.z, w, acc.z);
            acc.w = fmaf(v.w, w, acc.w);
            p = pn;
        }
        float4* o = (float4*)(out + (size_t)dst * 128) + lane;
        float4 cur = *o;
        cur.x += acc.x; cur.y += acc.y; cur.z += acc.z; cur.w += acc.w;
        *o = cur;
    } else {
        float2 acc = make_float2(0.f, 0.f);
        int p = (beg < end) ? g_epack[beg] : 0;
        for (int j = beg; j < end; j++) {
            int pn = (j + 1 < end) ? g_epack[j + 1] : 0;
            float w = g_inv[(dst << 3) + (p & 7)];
            float2 v = ((const float2*)(xw + (size_t)p * 64))[lane];
            acc.x = fmaf(v.x, w, acc.x);
            acc.y = fmaf(v.y, w, acc.y);
            p = pn;
        }
        float2* o = (float2*)(out + (size_t)dst * 64) + lane;
        float2 cur = *o;
        cur.x += acc.x; cur.y += acc.y;
        *o = cur;
    }
}

// ---------------- launch ----------------
extern "C" void kernel_launch(void* const* d_in, const int* in_sizes, int n_in,
                              void* d_out, int out_size) {
    const float* x     = (const float*)d_in[0];
    const void*  ei    = d_in[1];              // int64 or int32, detected on device
    const void*  et    = d_in[2];
    const float* W1    = (const float*)d_in[3];
    const float* root1 = (const float*)d_in[4];
    const float* b1    = (const float*)d_in[5];
    const float* W2    = (const float*)d_in[6];
    const float* root2 = (const float*)d_in[7];
    const float* b2    = (const float*)d_in[8];
    float* out = (float*)d_out;

    const int M = in_sizes[0] / 128;   // 50000 nodes
    const int E = in_sizes[2];         // 500000 edges

    // ---- index dtype detection + CSR build (shared by both layers) ----
    detect_kernel<<<1, 256>>>((const int*)ei);
    int nz = M * 8 > E ? M * 8 : E;
    zero_kernel<<<(nz + 255) / 256, 256>>>(M * 8, E);
    count_kernel<<<(E + 255) / 256, 256>>>(ei, et, E);
    inv_deg_kernel<<<(M + 255) / 256, 256>>>(M);
    fill_kernel<<<(E + 255) / 256, 256>>>(ei, et, E);

    dim3 g1((M + 127) / 128, 9);
    int gblocks = (M * 32 + 255) / 256;  // one warp per dst

    // ---- layer 1 ----
    rgcn_gemm<128, 1><<<g1, 256>>>(x, W1, root1, b1, nullptr, M);
    gather_kernel<128, 1><<<gblocks, 256>>>(nullptr, M);

    // ---- layer 2 (ReLU fused into A-tile load) ----
    rgcn_gemm<64, 2><<<g1, 128>>>(nullptr, W2, root2, b2, out, M);
    gather_kernel<64, 2><<<gblocks, 256>>>(out, M);

    // ---- final activation ----
    int no = M * 64;
    sigmoid_kernel<<<(no + 255) / 256, 256>>>(out, no);
}

// round 7
// speedup vs baseline: 1.7413x; 1.7413x over previous
#include <cuda_runtime.h>
#include <cuda_bf16.h>
#include <math.h>

#define NMAX 50048   // 391*128 padded so GEMM tile reads stay in-bounds
#define EMAX 500000

// ---------------- static scratch (no allocations allowed) ----------------
__device__ __nv_bfloat16 g_xaggh[(size_t)NMAX * 1024];  // per-(dst,rel) mean, hi
__device__ __nv_bfloat16 g_xaggl[(size_t)NMAX * 1024];  // lo
__device__ __nv_bfloat16 g_xh[(size_t)NMAX * 128];      // root-input, hi
__device__ __nv_bfloat16 g_xl[(size_t)NMAX * 128];      // lo
__device__ float g_h[(size_t)NMAX * 128];               // layer1 output
__device__ __nv_bfloat16 g_wb1h[128 * 1152];  // layer1 stacked W (n-major), hi
__device__ __nv_bfloat16 g_wb1l[128 * 1152];
__device__ __nv_bfloat16 g_wb2h[64 * 1152];   // layer2
__device__ __nv_bfloat16 g_wb2l[64 * 1152];
__device__ int   g_cnt[NMAX * 8];
__device__ float g_inv[NMAX * 8];
__device__ int   g_off8[NMAX * 8];
__device__ int   g_cur8[NMAX * 8];
__device__ int   g_epack[EMAX];   // src node id, grouped per (dst, rel)
__device__ int   g_total;
__device__ int   g_idx64;

// ---------------- helpers ----------------
__device__ __forceinline__ unsigned smem_u32(const void* p) {
    unsigned a;
    asm("{ .reg .u64 t; cvta.to.shared.u64 t, %1; cvt.u32.u64 %0, t; }"
        : "=r"(a) : "l"(p));
    return a;
}
__device__ __forceinline__ unsigned lds32(unsigned a) {
    unsigned v;
    asm volatile("ld.shared.b32 %0, [%1];" : "=r"(v) : "r"(a));
    return v;
}
__device__ __forceinline__ void cp16(unsigned dst, const void* src) {
    asm volatile("cp.async.cg.shared.global [%0], [%1], 16;"
                 :: "r"(dst), "l"(src) : "memory");
}
#define CP_COMMIT() asm volatile("cp.async.commit_group;" ::: "memory")
#define CP_WAIT(n)  asm volatile("cp.async.wait_group %0;" :: "n"(n) : "memory")

__device__ __forceinline__ void mma16816(float* c, const unsigned* a, const unsigned* b) {
    asm volatile("mma.sync.aligned.m16n8k16.row.col.f32.bf16.bf16.f32 "
                 "{%0,%1,%2,%3}, {%4,%5,%6,%7}, {%8,%9}, {%0,%1,%2,%3};"
                 : "+f"(c[0]), "+f"(c[1]), "+f"(c[2]), "+f"(c[3])
                 : "r"(a[0]), "r"(a[1]), "r"(a[2]), "r"(a[3]),
                   "r"(b[0]), "r"(b[1]));
}
__device__ __forceinline__ unsigned pack2(float a, float b) {
    return ((unsigned)__bfloat16_as_ushort(__float2bfloat16(b)) << 16)
         | (unsigned)__bfloat16_as_ushort(__float2bfloat16(a));
}
__device__ __forceinline__ void split_bf16(float v, float& hi_f, unsigned short& h,
                                           unsigned short& l) {
    __nv_bfloat16 hb = __float2bfloat16(v);
    hi_f = __bfloat162float(hb);
    h = __bfloat16_as_ushort(hb);
    l = __bfloat16_as_ushort(__float2bfloat16(v - hi_f));
}

// ---------------- index dtype detection ----------------
__global__ void detect_kernel(const int* __restrict__ ei32) {
    __shared__ int any;
    if (threadIdx.x == 0) any = 0;
    __syncthreads();
    if (ei32[2 * threadIdx.x + 1] != 0) atomicOr(&any, 1);
    __syncthreads();
    if (threadIdx.x == 0) g_idx64 = (any == 0) ? 1 : 0;
}
__device__ __forceinline__ int load_idx(const void* p, long long i) {
    if (g_idx64) return (int)((const long long*)p)[i];
    return ((const int*)p)[i];
}

// ---------------- CSR build (per (dst, rel) segments) ----------------
__global__ void zero_kernel(int n8) {
    int i = blockIdx.x * blockDim.x + threadIdx.x;
    if (i < n8) g_cnt[i] = 0;
    if (i == 0) g_total = 0;
}
__global__ void count_kernel(const void* __restrict__ ei,
                             const void* __restrict__ et, int E) {
    int e = blockIdx.x * blockDim.x + threadIdx.x;
    if (e < E) {
        int dst = load_idx(ei, (long long)E + e);
        int r   = load_idx(et, e);
        if ((unsigned)dst < 50000u && (unsigned)r < 8u)
            atomicAdd(&g_cnt[dst * 8 + r], 1);
    }
}
__global__ void off_kernel(int n8) {
    int i = blockIdx.x * blockDim.x + threadIdx.x;
    if (i >= n8) return;
    int c = g_cnt[i];
    g_inv[i] = 1.0f / (float)(c > 0 ? c : 1);
    int off = atomicAdd(&g_total, c);
    g_off8[i] = off;
    g_cur8[i] = off;
}
__global__ void fill_kernel(const void* __restrict__ ei,
                            const void* __restrict__ et, int E) {
    int e = blockIdx.x * blockDim.x + threadIdx.x;
    if (e < E) {
        int src = load_idx(ei, e);
        int dst = load_idx(ei, (long long)E + e);
        int r   = load_idx(et, e);
        if ((unsigned)src < 50000u && (unsigned)dst < 50000u && (unsigned)r < 8u) {
            int pos = atomicAdd(&g_cur8[dst * 8 + r], 1);
            g_epack[pos] = src;
        }
    }
}

// ---------------- W pack: stacked [n][k=1152] bf16 hi/lo ----------------
__global__ void pack_kernel(const float* __restrict__ W1, const float* __restrict__ root1,
                            const float* __restrict__ W2, const float* __restrict__ root2) {
    int idx = blockIdx.x * blockDim.x + threadIdx.x;
    const int T1 = 128 * 1152;
    const int T2 = 64 * 1152;
    if (idx < T1) {
        int n = idx / 1152, k = idx % 1152;
        float w = (k < 1024) ? W1[((size_t)(k >> 7) * 128 + (k & 127)) * 128 + n]
                             : root1[(size_t)(k - 1024) * 128 + n];
        float hf; unsigned short h, l;
        split_bf16(w, hf, h, l);
        g_wb1h[idx] = __ushort_as_bfloat16(h);
        g_wb1l[idx] = __ushort_as_bfloat16(l);
    } else if (idx < T1 + T2) {
        int j = idx - T1;
        int n = j / 1152, k = j % 1152;
        float w = (k < 1024) ? W2[((size_t)(k >> 7) * 128 + (k & 127)) * 64 + n]
                             : root2[(size_t)(k - 1024) * 64 + n];
        float hf; unsigned short h, l;
        split_bf16(w, hf, h, l);
        g_wb2h[j] = __ushort_as_bfloat16(h);
        g_wb2l[j] = __ushort_as_bfloat16(l);
    }
}

// ---------------- root-input conversion: fp32 -> bf16 hi/lo ----------------
template <int LAYER>
__global__ void conv_kernel(const float* __restrict__ xin, int nq) {
    int i = blockIdx.x * blockDim.x + threadIdx.x;  // one float4 per thread
    if (i >= nq) return;
    const float* src = (LAYER == 1) ? xin : (const float*)g_h;
    float4 v = ((const float4*)src)[i];
    if (LAYER == 2) {
        v.x = fmaxf(v.x, 0.f); v.y = fmaxf(v.y, 0.f);
        v.z = fmaxf(v.z, 0.f); v.w = fmaxf(v.w, 0.f);
    }
    float hx, hy, hz, hw;
    unsigned short a, b, c, d, e, f, g2, h2;
    split_bf16(v.x, hx, a, e); split_bf16(v.y, hy, b, f);
    split_bf16(v.z, hz, c, g2); split_bf16(v.w, hw, d, h2);
    uint2 uh = make_uint2(((unsigned)b << 16) | a, ((unsigned)d << 16) | c);
    uint2 ul = make_uint2(((unsigned)f << 16) | e, ((unsigned)h2 << 16) | g2);
    *(uint2*)(g_xh + (size_t)i * 4) = uh;
    *(uint2*)(g_xl + (size_t)i * 4) = ul;
}

// ---------------- aggregation: xagg[dst,r,:] = mean_{e in (dst,r)} x[src] ----
// One warp per dst; relations processed sequentially; writes bf16 hi/lo.
template <int LAYER>
__global__ void __launch_bounds__(256)
agg_kernel(const float* __restrict__ xin, int N) {
    const float* src = (LAYER == 1) ? xin : (const float*)g_h;
    int warp = (blockIdx.x * 256 + threadIdx.x) >> 5;
    int lane = threadIdx.x & 31;
    if (warp >= N) return;
    int dst = warp;

    #pragma unroll 1
    for (int r = 0; r < 8; r++) {
        int idx8 = dst * 8 + r;
        int c = g_cnt[idx8];
        int off = g_off8[idx8];
        float4 acc = make_float4(0.f, 0.f, 0.f, 0.f);
        for (int j = 0; j < c; j++) {
            int s = g_epack[off + j];
            float4 v = ((const float4*)(src + (size_t)s * 128))[lane];
            if (LAYER == 2) {
                v.x = fmaxf(v.x, 0.f); v.y = fmaxf(v.y, 0.f);
                v.z = fmaxf(v.z, 0.f); v.w = fmaxf(v.w, 0.f);
            }
            acc.x += v.x; acc.y += v.y; acc.z += v.z; acc.w += v.w;
        }
        float w = g_inv[idx8];
        acc.x *= w; acc.y *= w; acc.z *= w; acc.w *= w;

        float hx, hy, hz, hw;
        unsigned short a, b2, c2, d, e, f, g2, h2;
        split_bf16(acc.x, hx, a, e); split_bf16(acc.y, hy, b2, f);
        split_bf16(acc.z, hz, c2, g2); split_bf16(acc.w, hw, d, h2);
        size_t base = (size_t)dst * 1024 + r * 128 + lane * 4;
        *(uint2*)(g_xaggh + base) = make_uint2(((unsigned)b2 << 16) | a,
                                               ((unsigned)d << 16) | c2);
        *(uint2*)(g_xaggl + base) = make_uint2(((unsigned)f << 16) | e,
                                               ((unsigned)h2 << 16) | g2);
    }
}

// ---------------- GEMM: out[m,:] = A[m, 0:1152] @ Wstack + bias -------------
// A = [xagg (1024) ++ xroot (128)], both bf16 hi/lo. 3 mma products:
// AhBh + AhBl + AlBh, fp32 accumulate. BM=128, BN=FOUT, K chunked by 64,
// cp.async double-buffered, swizzled 128B smem rows. 256 threads, 8 warps.
template <int FOUT, int LAYER>
__global__ void __launch_bounds__(256, 1)
mm_kernel(const float* __restrict__ bias, float* __restrict__ outExt, int M) {
    constexpr int WN = (FOUT == 128) ? 64 : 32;
    constexpr int NFR = WN / 8;
    constexpr int ABYT = 128 * 128;          // 128 rows x 128B
    constexpr int BBYT = FOUT * 128;
    constexpr int STAGE = 2 * ABYT + 2 * BBYT;
    constexpr int NCHUNK = 18;               // 1152 / 64

    extern __shared__ char smem[];
    const unsigned sbase = smem_u32(smem);

    const __nv_bfloat16* wbh = (LAYER == 1) ? g_wb1h : g_wb2h;
    const __nv_bfloat16* wbl = (LAYER == 1) ? g_wb1l : g_wb2l;
    float* outp = (LAYER == 1) ? g_h : outExt;

    const int tid = threadIdx.x;
    const int wid = tid >> 5, lane = tid & 31;
    const int wm = wid & 3, wn = wid >> 2;
    const int g = lane >> 2, t = lane & 3;
    const int m0 = blockIdx.x * 128;

    float acc[2][NFR][4];
    #pragma unroll
    for (int mi = 0; mi < 2; mi++)
        #pragma unroll
        for (int ni = 0; ni < NFR; ni++)
            #pragma unroll
            for (int q = 0; q < 4; q++) acc[mi][ni][q] = 0.f;

    // -------- chunk loader (cp.async) --------
    auto load_chunk = [&](int c, int s) {
        const unsigned ah = sbase + s * STAGE;
        const unsigned al = ah + ABYT;
        const unsigned bh = al + ABYT;
        const unsigned bl = bh + BBYT;
        // A: 2 arrays x 128 rows x 8 x 16B
        #pragma unroll
        for (int i = 0; i < 8; i++) {
            int idx = tid + i * 256;
            int arr = idx >> 10;
            int rem = idx & 1023;
            int row = rem >> 3, t16 = rem & 7;
            const __nv_bfloat16* s0;
            size_t go;
            if (c < 16) {
                s0 = arr ? g_xaggl : g_xaggh;
                go = (size_t)(m0 + row) * 1024 + c * 64 + t16 * 8;
            } else {
                s0 = arr ? g_xl : g_xh;
                go = (size_t)(m0 + row) * 128 + (c - 16) * 64 + t16 * 8;
            }
            unsigned d = (arr ? al : ah) + row * 128 + ((t16 * 16) ^ ((row & 7) * 16));
            cp16(d, s0 + go);
        }
        // B: 2 arrays x FOUT rows x 8 x 16B
        #pragma unroll
        for (int i = 0; i < (FOUT == 128 ? 8 : 4); i++) {
            int idx = tid + i * 256;
            int arr = idx / (FOUT * 8);
            int rem = idx % (FOUT * 8);
            int row = rem >> 3, t16 = rem & 7;
            const __nv_bfloat16* s0 = arr ? wbl : wbh;
            size_t go = (size_t)row * 1152 + c * 64 + t16 * 8;
            unsigned d = (arr ? bl : bh) + row * 128 + ((t16 * 16) ^ ((row & 7) * 16));
            cp16(d, s0 + go);
        }
    };

    load_chunk(0, 0);
    CP_COMMIT();

    #pragma unroll 1
    for (int c = 0; c < NCHUNK; c++) {
        if (c < NCHUNK - 1) {
            load_chunk(c + 1, (c + 1) & 1);
            CP_COMMIT();
            CP_WAIT(1);
        } else {
            CP_WAIT(0);
        }
        __syncthreads();

        const int s = c & 1;
        const unsigned sAh = sbase + s * STAGE;
        const unsigned sAl = sAh + ABYT;
        const unsigned sBh = sAl + ABYT;
        const unsigned sBl = sBh + BBYT;

        #pragma unroll
        for (int ks = 0; ks < 4; ks++) {
            const int kb = ks * 32 + t * 4;
            unsigned ahf[2][4], alf[2][4], bhf[NFR][2], blf[NFR][2];
            #pragma unroll
            for (int mi = 0; mi < 2; mi++) {
                int r0 = wm * 32 + mi * 16 + g;
                int r1 = r0 + 8;
                unsigned o00 = r0 * 128 + (kb ^ ((r0 & 7) * 16));
                unsigned o10 = r1 * 128 + (kb ^ ((r1 & 7) * 16));
                unsigned o01 = r0 * 128 + ((kb + 16) ^ ((r0 & 7) * 16));
                unsigned o11 = r1 * 128 + ((kb + 16) ^ ((r1 & 7) * 16));
                ahf[mi][0] = lds32(sAh + o00); ahf[mi][1] = lds32(sAh + o10);
                ahf[mi][2] = lds32(sAh + o01); ahf[mi][3] = lds32(sAh + o11);
                alf[mi][0] = lds32(sAl + o00); alf[mi][1] = lds32(sAl + o10);
                alf[mi][2] = lds32(sAl + o01); alf[mi][3] = lds32(sAl + o11);
            }
            #pragma unroll
            for (int ni = 0; ni < NFR; ni++) {
                int nr = wn * WN + ni * 8 + g;
                unsigned o0 = nr * 128 + (kb ^ ((nr & 7) * 16));
                unsigned o1 = nr * 128 + ((kb + 16) ^ ((nr & 7) * 16));
                bhf[ni][0] = lds32(sBh + o0); bhf[ni][1] = lds32(sBh + o1);
                blf[ni][0] = lds32(sBl + o0); blf[ni][1] = lds32(sBl + o1);
            }
            #pragma unroll
            for (int mi = 0; mi < 2; mi++)
                #pragma unroll
                for (int ni = 0; ni < NFR; ni++) {
                    mma16816(acc[mi][ni], ahf[mi], bhf[ni]);
                    mma16816(acc[mi][ni], ahf[mi], blf[ni]);
                    mma16816(acc[mi][ni], alf[mi], bhf[ni]);
                }
        }
        __syncthreads();
    }

    // -------- epilogue --------
    #pragma unroll
    for (int mi = 0; mi < 2; mi++) {
        int row0 = m0 + wm * 32 + mi * 16 + g;
        #pragma unroll
        for (int ni = 0; ni < NFR; ni++) {
            int col = wn * WN + ni * 8 + 2 * t;
            float b0 = bias[col], b1 = bias[col + 1];
            float v0 = acc[mi][ni][0] + b0, v1 = acc[mi][ni][1] + b1;
            float v2 = acc[mi][ni][2] + b0, v3 = acc[mi][ni][3] + b1;
            if (LAYER == 2) {
                v0 = 1.0f / (1.0f + expf(-v0));
                v1 = 1.0f / (1.0f + expf(-v1));
                v2 = 1.0f / (1.0f + expf(-v2));
                v3 = 1.0f / (1.0f + expf(-v3));
            }
            if (row0 < M)
                *(float2*)(outp + (size_t)row0 * FOUT + col) = make_float2(v0, v1);
            if (row0 + 8 < M)
                *(float2*)(outp + (size_t)(row0 + 8) * FOUT + col) = make_float2(v2, v3);
        }
    }
}

// ---------------- launch ----------------
extern "C" void kernel_launch(void* const* d_in, const int* in_sizes, int n_in,
                              void* d_out, int out_size) {
    const float* x     = (const float*)d_in[0];
    const void*  ei    = d_in[1];
    const void*  et    = d_in[2];
    const float* W1    = (const float*)d_in[3];
    const float* root1 = (const float*)d_in[4];
    const float* b1    = (const float*)d_in[5];
    const float* W2    = (const float*)d_in[6];
    const float* root2 = (const float*)d_in[7];
    const float* b2    = (const float*)d_in[8];
    float* out = (float*)d_out;

    const int M = in_sizes[0] / 128;   // 50000 nodes
    const int E = in_sizes[2];         // 500000 edges

    const int SM1 = 2 * (2 * 128 * 128 + 2 * 128 * 128);  // 131072
    const int SM2 = 2 * (2 * 128 * 128 + 2 * 64 * 128);   // 98304
    static int configured = 0;
    if (!configured) {
        cudaFuncSetAttribute((const void*)&mm_kernel<128, 1>,
                             cudaFuncAttributeMaxDynamicSharedMemorySize, SM1);
        cudaFuncSetAttribute((const void*)&mm_kernel<64, 2>,
                             cudaFuncAttributeMaxDynamicSharedMemorySize, SM2);
        configured = 1;
    }

    // ---- CSR build (per (dst, rel) segments; shared by both layers) ----
    detect_kernel<<<1, 256>>>((const int*)ei);
    int n8 = M * 8;
    zero_kernel<<<(n8 + 255) / 256, 256>>>(n8);
    count_kernel<<<(E + 255) / 256, 256>>>(ei, et, E);
    off_kernel<<<(n8 + 255) / 256, 256>>>(n8);
    fill_kernel<<<(E + 255) / 256, 256>>>(ei, et, E);

    // ---- stacked-W pack ----
    int ptot = 128 * 1152 + 64 * 1152;
    pack_kernel<<<(ptot + 255) / 256, 256>>>(W1, root1, W2, root2);

    const int mblocks = (M + 127) / 128;
    const int ablocks = (M * 32 + 255) / 256;
    const int cblocks = (M * 32 + 255) / 256;   // N*128/4 threads

    // ---- layer 1 ----
    conv_kernel<1><<<cblocks, 256>>>(x, M * 32);
    agg_kernel<1><<<ablocks, 256>>>(x, M);
    mm_kernel<128, 1><<<mblocks, 256, SM1>>>(b1, nullptr, M);

    // ---- layer 2 (ReLU fused into conv/agg reads, sigmoid into epilogue) ----
    conv_kernel<2><<<cblocks, 256>>>(nullptr, M * 32);
    agg_kernel<2><<<ablocks, 256>>>(nullptr, M);
    mm_kernel<64, 2><<<mblocks, 256, SM2>>>(b2, out, M);
}

// round 8
// speedup vs baseline: 2.0256x; 1.1633x over previous
#include <cuda_runtime.h>
#include <cuda_fp16.h>
#include <math.h>

#define NMAX 50048   // 391*128 padded so GEMM tile reads stay in-bounds
#define EMAX 500000

// ---------------- static scratch (no allocations allowed) ----------------
__device__ __half g_xagg1 [(size_t)NMAX * 1024];  // L1 per-(dst,rel) mean, fp16
__device__ __half g_xagg2h[(size_t)NMAX * 1024];  // L2 mean hi
__device__ __half g_xagg2l[(size_t)NMAX * 1024];  // L2 mean lo (x 2^11)
__device__ __half g_xf [(size_t)NMAX * 128];      // L1 root input, fp16
__device__ __half g_hfh[(size_t)NMAX * 128];      // relu(h) hi
__device__ __half g_hfl[(size_t)NMAX * 128];      // relu(h) lo (x 2^11)
__device__ __half g_wb1h[128 * 1152];             // L1 stacked W hi
__device__ __half g_wb1l[128 * 1152];             // L1 stacked W lo (x 2^11)
__device__ __half g_wb2h[64 * 1152];
__device__ __half g_wb2l[64 * 1152];
__device__ int   g_cnt[NMAX * 8];
__device__ float g_inv[NMAX * 8];
__device__ int   g_off8[NMAX * 8];
__device__ int   g_cur8[NMAX * 8];
__device__ int   g_epack[EMAX];
__device__ int   g_total;
__device__ int   g_idx64;

#define SC2048   2048.0f
#define INV2048  4.8828125e-4f
#define H2_INV2048 0x10001000u   // half2(2^-11, 2^-11)

// ---------------- helpers ----------------
__device__ __forceinline__ unsigned smem_u32(const void* p) {
    unsigned a;
    asm("{ .reg .u64 t; cvta.to.shared.u64 t, %1; cvt.u32.u64 %0, t; }"
        : "=r"(a) : "l"(p));
    return a;
}
__device__ __forceinline__ unsigned lds32(unsigned a) {
    unsigned v;
    asm volatile("ld.shared.b32 %0, [%1];" : "=r"(v) : "r"(a));
    return v;
}
__device__ __forceinline__ void cp16(unsigned dst, const void* src) {
    asm volatile("cp.async.cg.shared.global [%0], [%1], 16;"
                 :: "r"(dst), "l"(src) : "memory");
}
#define CP_COMMIT() asm volatile("cp.async.commit_group;" ::: "memory")
#define CP_WAIT(n)  asm volatile("cp.async.wait_group %0;" :: "n"(n) : "memory")

__device__ __forceinline__ void mma_fp16(float* c, const unsigned* a, const unsigned* b) {
    asm volatile("mma.sync.aligned.m16n8k16.row.col.f32.f16.f16.f32 "
                 "{%0,%1,%2,%3}, {%4,%5,%6,%7}, {%8,%9}, {%0,%1,%2,%3};"
                 : "+f"(c[0]), "+f"(c[1]), "+f"(c[2]), "+f"(c[3])
                 : "r"(a[0]), "r"(a[1]), "r"(a[2]), "r"(a[3]),
                   "r"(b[0]), "r"(b[1]));
}
__device__ __forceinline__ unsigned h2mul(unsigned v, unsigned s) {
    unsigned r;
    asm("mul.f16x2 %0, %1, %2;" : "=r"(r) : "r"(v), "r"(s));
    return r;
}

// ---------------- index dtype detection ----------------
__global__ void detect_kernel(const int* __restrict__ ei32) {
    __shared__ int any;
    if (threadIdx.x == 0) any = 0;
    __syncthreads();
    if (ei32[2 * threadIdx.x + 1] != 0) atomicOr(&any, 1);
    __syncthreads();
    if (threadIdx.x == 0) g_idx64 = (any == 0) ? 1 : 0;
}
__device__ __forceinline__ int load_idx(const void* p, long long i) {
    if (g_idx64) return (int)((const long long*)p)[i];
    return ((const int*)p)[i];
}

// ---------------- CSR build ----------------
__global__ void zero_kernel(int n8) {
    int i = blockIdx.x * blockDim.x + threadIdx.x;
    if (i < n8) g_cnt[i] = 0;
    if (i == 0) g_total = 0;
}
__global__ void count_kernel(const void* __restrict__ ei,
                             const void* __restrict__ et, int E) {
    int e = blockIdx.x * blockDim.x + threadIdx.x;
    if (e < E) {
        int dst = load_idx(ei, (long long)E + e);
        int r   = load_idx(et, e);
        if ((unsigned)dst < 50000u && (unsigned)r < 8u)
            atomicAdd(&g_cnt[dst * 8 + r], 1);
    }
}
// warp-aggregated slot grab: one atomic per warp instead of per thread
__global__ void off_kernel(int n8) {
    int i = blockIdx.x * blockDim.x + threadIdx.x;
    int lane = threadIdx.x & 31;
    int c = (i < n8) ? g_cnt[i] : 0;
    if (i < n8) g_inv[i] = 1.0f / (float)(c > 0 ? c : 1);
    int incl = c;
    #pragma unroll
    for (int d = 1; d < 32; d <<= 1) {
        int t = __shfl_up_sync(0xffffffffu, incl, d);
        if (lane >= d) incl += t;
    }
    int tot = __shfl_sync(0xffffffffu, incl, 31);
    int base = 0;
    if (lane == 0) base = atomicAdd(&g_total, tot);
    base = __shfl_sync(0xffffffffu, base, 0);
    if (i < n8) {
        int off = base + incl - c;
        g_off8[i] = off;
        g_cur8[i] = off;
    }
}
__global__ void fill_kernel(const void* __restrict__ ei,
                            const void* __restrict__ et, int E) {
    int e = blockIdx.x * blockDim.x + threadIdx.x;
    if (e < E) {
        int src = load_idx(ei, e);
        int dst = load_idx(ei, (long long)E + e);
        int r   = load_idx(et, e);
        if ((unsigned)src < 50000u && (unsigned)dst < 50000u && (unsigned)r < 8u) {
            int pos = atomicAdd(&g_cur8[dst * 8 + r], 1);
            g_epack[pos] = src;
        }
    }
}

// ---------------- W pack: stacked [n][k=1152], fp16 hi + lo*2^11 ----------------
__global__ void pack_kernel(const float* __restrict__ W1, const float* __restrict__ root1,
                            const float* __restrict__ W2, const float* __restrict__ root2) {
    int idx = blockIdx.x * blockDim.x + threadIdx.x;
    const int T1 = 128 * 1152;
    const int T2 = 64 * 1152;
    if (idx < T1) {
        int n = idx / 1152, k = idx % 1152;
        float w = (k < 1024) ? W1[((size_t)(k >> 7) * 128 + (k & 127)) * 128 + n]
                             : root1[(size_t)(k - 1024) * 128 + n];
        __half h = __float2half_rn(w);
        g_wb1h[idx] = h;
        g_wb1l[idx] = __float2half_rn((w - __half2float(h)) * SC2048);
    } else if (idx < T1 + T2) {
        int j = idx - T1;
        int n = j / 1152, k = j % 1152;
        float w = (k < 1024) ? W2[((size_t)(k >> 7) * 128 + (k & 127)) * 64 + n]
                             : root2[(size_t)(k - 1024) * 64 + n];
        __half h = __float2half_rn(w);
        g_wb2h[j] = h;
        g_wb2l[j] = __float2half_rn((w - __half2float(h)) * SC2048);
    }
}

// ---------------- L1 root input: fp32 x -> fp16 ----------------
__global__ void conv1_kernel(const float* __restrict__ x, int nq) {
    int i = blockIdx.x * blockDim.x + threadIdx.x;
    if (i >= nq) return;
    float4 v = ((const float4*)x)[i];
    __half2* d = (__half2*)(g_xf + (size_t)i * 4);
    d[0] = __floats2half2_rn(v.x, v.y);
    d[1] = __floats2half2_rn(v.z, v.w);
}

// ---------------- aggregation L1: mean of x[src] per (dst,r), fp16 out ----------
__global__ void __launch_bounds__(256)
agg1_kernel(const float* __restrict__ x, int N) {
    int warp = (blockIdx.x * 256 + threadIdx.x) >> 5;
    int lane = threadIdx.x & 31;
    if (warp >= N) return;
    int dst = warp;
    #pragma unroll 1
    for (int r = 0; r < 8; r++) {
        int idx8 = dst * 8 + r;
        int c = g_cnt[idx8];
        int off = g_off8[idx8];
        float4 acc = make_float4(0.f, 0.f, 0.f, 0.f);
        for (int j = 0; j < c; j++) {
            int s = g_epack[off + j];
            float4 v = ((const float4*)(x + (size_t)s * 128))[lane];
            acc.x += v.x; acc.y += v.y; acc.z += v.z; acc.w += v.w;
        }
        float w = g_inv[idx8];
        __half2* d = (__half2*)(g_xagg1 + (size_t)dst * 1024 + r * 128 + lane * 4);
        d[0] = __floats2half2_rn(acc.x * w, acc.y * w);
        d[1] = __floats2half2_rn(acc.z * w, acc.w * w);
    }
}

// ---------------- aggregation L2: mean of relu(h)[src] (fp16 hi/lo in, hi/lo out) --
__global__ void __launch_bounds__(256)
agg2_kernel(int N) {
    int warp = (blockIdx.x * 256 + threadIdx.x) >> 5;
    int lane = threadIdx.x & 31;
    if (warp >= N) return;
    int dst = warp;
    #pragma unroll 1
    for (int r = 0; r < 8; r++) {
        int idx8 = dst * 8 + r;
        int c = g_cnt[idx8];
        int off = g_off8[idx8];
        float4 acc = make_float4(0.f, 0.f, 0.f, 0.f);
        for (int j = 0; j < c; j++) {
            int s = g_epack[off + j];
            const __half2* ph = (const __half2*)(g_hfh + (size_t)s * 128) + lane * 2;
            const __half2* pl = (const __half2*)(g_hfl + (size_t)s * 128) + lane * 2;
            __half2 h0 = ph[0], h1 = ph[1], l0 = pl[0], l1 = pl[1];
            acc.x += __low2float(h0)  + __low2float(l0)  * INV2048;
            acc.y += __high2float(h0) + __high2float(l0) * INV2048;
            acc.z += __low2float(h1)  + __low2float(l1)  * INV2048;
            acc.w += __high2float(h1) + __high2float(l1) * INV2048;
        }
        float w = g_inv[idx8];
        float v0 = acc.x * w, v1 = acc.y * w, v2 = acc.z * w, v3 = acc.w * w;
        size_t base = (size_t)dst * 1024 + r * 128 + lane * 4;
        __half h0 = __float2half_rn(v0), h1 = __float2half_rn(v1);
        __half h2 = __float2half_rn(v2), h3 = __float2half_rn(v3);
        __half2* dh = (__half2*)(g_xagg2h + base);
        __half2* dl = (__half2*)(g_xagg2l + base);
        dh[0] = __halves2half2(h0, h1);
        dh[1] = __halves2half2(h2, h3);
        dl[0] = __floats2half2_rn((v0 - __half2float(h0)) * SC2048,
                                  (v1 - __half2float(h1)) * SC2048);
        dl[1] = __floats2half2_rn((v2 - __half2float(h2)) * SC2048,
                                  (v3 - __half2float(h3)) * SC2048);
    }
}

// ---------------- GEMM: out[m,:] = A[m,0:1152] @ Wstack + bias ----------------
// L1 (FOUT=128): A single fp16, B = Wh + Wl*2^11; D = Af*Bh + (Af*2^-11)*Bl'  (2 mma)
//   epilogue: relu, split to fp16 hi + lo*2^11 -> g_hfh/g_hfl
// L2 (FOUT=64):  A = Ah + Al*2^11, B = Wh + Wl*2^11;
//   D = Ah*Bh + (Ah*2^-11)*Bl' + (Al'*2^-11)*Bh  (3 mma); epilogue: sigmoid -> out
template <int FOUT, int LAYER>
__global__ void __launch_bounds__(256)
mm_kernel(const float* __restrict__ bias, float* __restrict__ outExt, int M) {
    constexpr int WN = (FOUT == 128) ? 64 : 32;
    constexpr int NFR = WN / 8;
    constexpr int TB = 128;                 // bytes per row (64 fp16)
    constexpr int ABYT = 128 * TB;          // 16 KB per A array
    constexpr int BBYT = FOUT * TB;
    constexpr int NA = (LAYER == 1) ? 1 : 2;
    constexpr int STAGE = NA * ABYT + 2 * BBYT;   // 48 KB both layers
    constexpr int NCHUNK = 18;

    extern __shared__ char smem[];
    const unsigned sbase = smem_u32(smem);

    const __half* wbh = (LAYER == 1) ? g_wb1h : g_wb2h;
    const __half* wbl = (LAYER == 1) ? g_wb1l : g_wb2l;

    const int tid = threadIdx.x;
    const int wid = tid >> 5, lane = tid & 31;
    const int wm = wid & 3, wn = wid >> 2;
    const int g = lane >> 2, t = lane & 3;
    const int m0 = blockIdx.x * 128;

    float acc[2][NFR][4];
    #pragma unroll
    for (int mi = 0; mi < 2; mi++)
        #pragma unroll
        for (int ni = 0; ni < NFR; ni++)
            #pragma unroll
            for (int q = 0; q < 4; q++) acc[mi][ni][q] = 0.f;

    auto load_chunk = [&](int c, int s) {
        const unsigned a0 = sbase + s * STAGE;
        const unsigned b0 = a0 + NA * ABYT;
        // ---- A ----
        #pragma unroll
        for (int i = 0; i < NA * 4; i++) {
            int idx = tid + i * 256;
            int arr = idx >> 10;          // 0 for L1; 0/1 for L2
            int rem = idx & 1023;
            int row = rem >> 3, t16 = rem & 7;
            const __half* s0;
            size_t go;
            if (LAYER == 1) {
                if (c < 16) { s0 = g_xagg1; go = (size_t)(m0 + row) * 1024 + c * 64 + t16 * 8; }
                else        { s0 = g_xf;    go = (size_t)(m0 + row) * 128 + (c - 16) * 64 + t16 * 8; }
            } else {
                if (c < 16) {
                    s0 = arr ? g_xagg2l : g_xagg2h;
                    go = (size_t)(m0 + row) * 1024 + c * 64 + t16 * 8;
                } else {
                    s0 = arr ? g_hfl : g_hfh;
                    go = (size_t)(m0 + row) * 128 + (c - 16) * 64 + t16 * 8;
                }
            }
            unsigned d = a0 + arr * ABYT + row * TB + ((t16 * 16) ^ ((row & 7) * 16));
            cp16(d, s0 + go);
        }
        // ---- B (hi + lo) ----
        #pragma unroll
        for (int i = 0; i < (FOUT == 128 ? 8 : 4); i++) {
            int idx = tid + i * 256;
            int arr = idx / (FOUT * 8);
            int rem = idx % (FOUT * 8);
            int row = rem >> 3, t16 = rem & 7;
            const __half* s0 = arr ? wbl : wbh;
            size_t go = (size_t)row * 1152 + c * 64 + t16 * 8;
            unsigned d = b0 + arr * BBYT + row * TB + ((t16 * 16) ^ ((row & 7) * 16));
            cp16(d, s0 + go);
        }
    };

    load_chunk(0, 0);
    CP_COMMIT();

    #pragma unroll 1
    for (int c = 0; c < NCHUNK; c++) {
        if (c < NCHUNK - 1) {
            load_chunk(c + 1, (c + 1) & 1);
            CP_COMMIT();
            CP_WAIT(1);
        } else {
            CP_WAIT(0);
        }
        __syncthreads();

        const int s = c & 1;
        const unsigned sA  = sbase + s * STAGE;
        const unsigned sAl = sA + ABYT;                 // L2 only
        const unsigned sBh = sA + NA * ABYT;
        const unsigned sBl = sBh + BBYT;

        #pragma unroll
        for (int ks = 0; ks < 4; ks++) {
            const int kb = ks * 32 + t * 4;
            unsigned ah[2][4], al[2][4], bh[NFR][2], bl[NFR][2];
            #pragma unroll
            for (int mi = 0; mi < 2; mi++) {
                int r0 = wm * 32 + mi * 16 + g;
                int r1 = r0 + 8;
                unsigned o00 = r0 * TB + (kb ^ ((r0 & 7) * 16));
                unsigned o10 = r1 * TB + (kb ^ ((r1 & 7) * 16));
                unsigned o01 = r0 * TB + ((kb + 16) ^ ((r0 & 7) * 16));
                unsigned o11 = r1 * TB + ((kb + 16) ^ ((r1 & 7) * 16));
                ah[mi][0] = lds32(sA + o00); ah[mi][1] = lds32(sA + o10);
                ah[mi][2] = lds32(sA + o01); ah[mi][3] = lds32(sA + o11);
                if (LAYER == 2) {
                    al[mi][0] = lds32(sAl + o00); al[mi][1] = lds32(sAl + o10);
                    al[mi][2] = lds32(sAl + o01); al[mi][3] = lds32(sAl + o11);
                }
            }
            #pragma unroll
            for (int ni = 0; ni < NFR; ni++) {
                int nr = wn * WN + ni * 8 + g;
                unsigned o0 = nr * TB + (kb ^ ((nr & 7) * 16));
                unsigned o1 = nr * TB + ((kb + 16) ^ ((nr & 7) * 16));
                bh[ni][0] = lds32(sBh + o0); bh[ni][1] = lds32(sBh + o1);
                bl[ni][0] = lds32(sBl + o0); bl[ni][1] = lds32(sBl + o1);
            }
            #pragma unroll
            for (int mi = 0; mi < 2; mi++) {
                unsigned as[4];
                #pragma unroll
                for (int q = 0; q < 4; q++) as[q] = h2mul(ah[mi][q], H2_INV2048);
                unsigned asl[4];
                if (LAYER == 2) {
                    #pragma unroll
                    for (int q = 0; q < 4; q++) asl[q] = h2mul(al[mi][q], H2_INV2048);
                }
                #pragma unroll
                for (int ni = 0; ni < NFR; ni++) {
                    mma_fp16(acc[mi][ni], ah[mi], bh[ni]);
                    mma_fp16(acc[mi][ni], as, bl[ni]);
                    if (LAYER == 2) mma_fp16(acc[mi][ni], asl, bh[ni]);
                }
            }
        }
        __syncthreads();
    }

    // -------- epilogue --------
    #pragma unroll
    for (int mi = 0; mi < 2; mi++) {
        int row0 = m0 + wm * 32 + mi * 16 + g;
        #pragma unroll
        for (int ni = 0; ni < NFR; ni++) {
            int col = wn * WN + ni * 8 + 2 * t;
            float b0 = bias[col], b1 = bias[col + 1];
            float v[4] = {acc[mi][ni][0] + b0, acc[mi][ni][1] + b1,
                          acc[mi][ni][2] + b0, acc[mi][ni][3] + b1};
            if (LAYER == 1) {
                #pragma unroll
                for (int q = 0; q < 4; q++) v[q] = fmaxf(v[q], 0.f);
                #pragma unroll
                for (int half = 0; half < 2; half++) {
                    int row = row0 + half * 8;
                    if (row >= M) continue;
                    __half h0 = __float2half_rn(v[half * 2]);
                    __half h1 = __float2half_rn(v[half * 2 + 1]);
                    *(__half2*)(g_hfh + (size_t)row * 128 + col) = __halves2half2(h0, h1);
                    *(__half2*)(g_hfl + (size_t)row * 128 + col) =
                        __floats2half2_rn((v[half * 2]     - __half2float(h0)) * SC2048,
                                          (v[half * 2 + 1] - __half2float(h1)) * SC2048);
                }
            } else {
                #pragma unroll
                for (int q = 0; q < 4; q++) v[q] = 1.0f / (1.0f + expf(-v[q]));
                if (row0 < M)
                    *(float2*)(outExt + (size_t)row0 * FOUT + col) = make_float2(v[0], v[1]);
                if (row0 + 8 < M)
                    *(float2*)(outExt + (size_t)(row0 + 8) * FOUT + col) = make_float2(v[2], v[3]);
            }
        }
    }
}

// ---------------- launch ----------------
extern "C" void kernel_launch(void* const* d_in, const int* in_sizes, int n_in,
                              void* d_out, int out_size) {
    const float* x     = (const float*)d_in[0];
    const void*  ei    = d_in[1];
    const void*  et    = d_in[2];
    const float* W1    = (const float*)d_in[3];
    const float* root1 = (const float*)d_in[4];
    const float* b1    = (const float*)d_in[5];
    const float* W2    = (const float*)d_in[6];
    const float* root2 = (const float*)d_in[7];
    const float* b2    = (const float*)d_in[8];
    float* out = (float*)d_out;

    const int M = in_sizes[0] / 128;   // 50000
    const int E = in_sizes[2];         // 500000

    const int SM1 = 2 * (1 * 128 * 128 + 2 * 128 * 128);  // 98304
    const int SM2 = 2 * (2 * 128 * 128 + 2 * 64 * 128);   // 98304
    static int configured = 0;
    if (!configured) {
        cudaFuncSetAttribute((const void*)&mm_kernel<128, 1>,
                             cudaFuncAttributeMaxDynamicSharedMemorySize, SM1);
        cudaFuncSetAttribute((const void*)&mm_kernel<64, 2>,
                             cudaFuncAttributeMaxDynamicSharedMemorySize, SM2);
        configured = 1;
    }

    // ---- CSR build ----
    detect_kernel<<<1, 256>>>((const int*)ei);
    int n8 = M * 8;
    zero_kernel<<<(n8 + 255) / 256, 256>>>(n8);
    count_kernel<<<(E + 255) / 256, 256>>>(ei, et, E);
    off_kernel<<<(n8 + 255) / 256, 256>>>(n8);
    fill_kernel<<<(E + 255) / 256, 256>>>(ei, et, E);

    // ---- W pack ----
    int ptot = 128 * 1152 + 64 * 1152;
    pack_kernel<<<(ptot + 255) / 256, 256>>>(W1, root1, W2, root2);

    const int mblocks = (M + 127) / 128;
    const int ablocks = (M * 32 + 255) / 256;

    // ---- layer 1 ----
    conv1_kernel<<<(M * 32 + 255) / 256, 256>>>(x, M * 32);
    agg1_kernel<<<ablocks, 256>>>(x, M);
    mm_kernel<128, 1><<<mblocks, 256, SM1>>>(b1, nullptr, M);

    // ---- layer 2 ----
    agg2_kernel<<<ablocks, 256>>>(M);
    mm_kernel<64, 2><<<mblocks, 256, SM2>>>(b2, out, M);
}

// round 9
// speedup vs baseline: 2.1512x; 1.0620x over previous
#include <cuda_runtime.h>
#include <cuda_fp16.h>
#include <math.h>

#define NMAX 50048   // 391*128 padded so GEMM tile reads stay in-bounds
#define EMAX 500000

// ---------------- static scratch (no allocations allowed) ----------------
__device__ __half g_xagg1[(size_t)NMAX * 1024];  // L1 per-(dst,rel) mean, fp16
__device__ __half g_xagg2[(size_t)NMAX * 1024];  // L2 per-(dst,rel) mean, fp16
__device__ __half g_xf[(size_t)NMAX * 128];      // L1 root input, fp16
__device__ __half g_hf[(size_t)NMAX * 128];      // relu(h), fp16
__device__ __half g_wb1[128 * 1152];             // L1 stacked W, fp16
__device__ __half g_wb2h[64 * 1152];             // L2 stacked W hi
__device__ __half g_wb2l[64 * 1152];             // L2 stacked W lo (x 2^11)
__device__ int   g_cnt[NMAX * 8];
__device__ int   g_off8[NMAX * 8];
__device__ int   g_cur8[NMAX * 8];
__device__ int   g_epack[EMAX];
__device__ int   g_total;
__device__ int   g_idx64;

#define SC2048   2048.0f
#define H2_INV2048 0x10001000u   // half2(2^-11, 2^-11)

// ---------------- helpers ----------------
__device__ __forceinline__ unsigned smem_u32(const void* p) {
    unsigned a;
    asm("{ .reg .u64 t; cvta.to.shared.u64 t, %1; cvt.u32.u64 %0, t; }"
        : "=r"(a) : "l"(p));
    return a;
}
__device__ __forceinline__ unsigned lds32(unsigned a) {
    unsigned v;
    asm volatile("ld.shared.b32 %0, [%1];" : "=r"(v) : "r"(a));
    return v;
}
__device__ __forceinline__ void cp16(unsigned dst, const void* src) {
    asm volatile("cp.async.cg.shared.global [%0], [%1], 16;"
                 :: "r"(dst), "l"(src) : "memory");
}
#define CP_COMMIT() asm volatile("cp.async.commit_group;" ::: "memory")
#define CP_WAIT(n)  asm volatile("cp.async.wait_group %0;" :: "n"(n) : "memory")

__device__ __forceinline__ void mma_fp16(float* c, const unsigned* a, const unsigned* b) {
    asm volatile("mma.sync.aligned.m16n8k16.row.col.f32.f16.f16.f32 "
                 "{%0,%1,%2,%3}, {%4,%5,%6,%7}, {%8,%9}, {%0,%1,%2,%3};"
                 : "+f"(c[0]), "+f"(c[1]), "+f"(c[2]), "+f"(c[3])
                 : "r"(a[0]), "r"(a[1]), "r"(a[2]), "r"(a[3]),
                   "r"(b[0]), "r"(b[1]));
}
__device__ __forceinline__ unsigned h2mul(unsigned v, unsigned s) {
    unsigned r;
    asm("mul.f16x2 %0, %1, %2;" : "=r"(r) : "r"(v), "r"(s));
    return r;
}

// ---------------- index dtype detection ----------------
__global__ void detect_kernel(const int* __restrict__ ei32) {
    __shared__ int any;
    if (threadIdx.x == 0) any = 0;
    __syncthreads();
    if (ei32[2 * threadIdx.x + 1] != 0) atomicOr(&any, 1);
    __syncthreads();
    if (threadIdx.x == 0) g_idx64 = (any == 0) ? 1 : 0;
}
__device__ __forceinline__ int load_idx(const void* p, long long i) {
    if (g_idx64) return (int)((const long long*)p)[i];
    return ((const int*)p)[i];
}

// ---------------- CSR build ----------------
__global__ void zero_kernel(int n8) {
    int i = blockIdx.x * blockDim.x + threadIdx.x;
    if (i < n8) g_cnt[i] = 0;
    if (i == 0) g_total = 0;
}
__global__ void count_kernel(const void* __restrict__ ei,
                             const void* __restrict__ et, int E) {
    int e = blockIdx.x * blockDim.x + threadIdx.x;
    if (e < E) {
        int dst = load_idx(ei, (long long)E + e);
        int r   = load_idx(et, e);
        if ((unsigned)dst < 50000u && (unsigned)r < 8u)
            atomicAdd(&g_cnt[dst * 8 + r], 1);
    }
}
// warp-aggregated slot grab (offsets only)
__global__ void off_kernel(int n8) {
    int i = blockIdx.x * blockDim.x + threadIdx.x;
    int lane = threadIdx.x & 31;
    int c = (i < n8) ? g_cnt[i] : 0;
    int incl = c;
    #pragma unroll
    for (int d = 1; d < 32; d <<= 1) {
        int t = __shfl_up_sync(0xffffffffu, incl, d);
        if (lane >= d) incl += t;
    }
    int tot = __shfl_sync(0xffffffffu, incl, 31);
    int base = 0;
    if (lane == 0) base = atomicAdd(&g_total, tot);
    base = __shfl_sync(0xffffffffu, base, 0);
    if (i < n8) {
        int off = base + incl - c;
        g_off8[i] = off;
        g_cur8[i] = off;
    }
}
__global__ void fill_kernel(const void* __restrict__ ei,
                            const void* __restrict__ et, int E) {
    int e = blockIdx.x * blockDim.x + threadIdx.x;
    if (e < E) {
        int src = load_idx(ei, e);
        int dst = load_idx(ei, (long long)E + e);
        int r   = load_idx(et, e);
        if ((unsigned)src < 50000u && (unsigned)dst < 50000u && (unsigned)r < 8u) {
            int pos = atomicAdd(&g_cur8[dst * 8 + r], 1);
            g_epack[pos] = src;
        }
    }
}

// ---------------- W pack: stacked [n][k=1152] ----------------
// L1: fp16 only. L2: fp16 hi + lo*2^11.
__global__ void pack_kernel(const float* __restrict__ W1, const float* __restrict__ root1,
                            const float* __restrict__ W2, const float* __restrict__ root2) {
    int idx = blockIdx.x * blockDim.x + threadIdx.x;
    const int T1 = 128 * 1152;
    const int T2 = 64 * 1152;
    if (idx < T1) {
        int n = idx / 1152, k = idx % 1152;
        float w = (k < 1024) ? W1[((size_t)(k >> 7) * 128 + (k & 127)) * 128 + n]
                             : root1[(size_t)(k - 1024) * 128 + n];
        g_wb1[idx] = __float2half_rn(w);
    } else if (idx < T1 + T2) {
        int j = idx - T1;
        int n = j / 1152, k = j % 1152;
        float w = (k < 1024) ? W2[((size_t)(k >> 7) * 128 + (k & 127)) * 64 + n]
                             : root2[(size_t)(k - 1024) * 64 + n];
        __half h = __float2half_rn(w);
        g_wb2h[j] = h;
        g_wb2l[j] = __float2half_rn((w - __half2float(h)) * SC2048);
    }
}

// ---------------- L1 root input: fp32 x -> fp16 ----------------
__global__ void conv1_kernel(const float* __restrict__ x, int nq) {
    int i = blockIdx.x * blockDim.x + threadIdx.x;
    if (i >= nq) return;
    float4 v = ((const float4*)x)[i];
    __half2* d = (__half2*)(g_xf + (size_t)i * 4);
    d[0] = __floats2half2_rn(v.x, v.y);
    d[1] = __floats2half2_rn(v.z, v.w);
}

// ---------------- aggregation: one warp per (dst, rel) segment ----------------
// L1: reads fp32 x rows; L2: reads fp16 relu(h) rows. Both write fp16 means.
__global__ void __launch_bounds__(256)
agg1_kernel(const float* __restrict__ x, int n8) {
    int seg = (blockIdx.x * 256 + threadIdx.x) >> 5;
    int lane = threadIdx.x & 31;
    if (seg >= n8) return;
    int c = g_cnt[seg];
    int off = g_off8[seg];
    float4 acc = make_float4(0.f, 0.f, 0.f, 0.f);
    for (int j = 0; j < c; j++) {
        int s = g_epack[off + j];
        float4 v = ((const float4*)(x + (size_t)s * 128))[lane];
        acc.x += v.x; acc.y += v.y; acc.z += v.z; acc.w += v.w;
    }
    float w = 1.0f / (float)(c > 0 ? c : 1);
    __half2* d = (__half2*)(g_xagg1 + (size_t)seg * 128 + lane * 4);
    d[0] = __floats2half2_rn(acc.x * w, acc.y * w);
    d[1] = __floats2half2_rn(acc.z * w, acc.w * w);
}

__global__ void __launch_bounds__(256)
agg2_kernel(int n8) {
    int seg = (blockIdx.x * 256 + threadIdx.x) >> 5;
    int lane = threadIdx.x & 31;
    if (seg >= n8) return;
    int c = g_cnt[seg];
    int off = g_off8[seg];
    float4 acc = make_float4(0.f, 0.f, 0.f, 0.f);
    for (int j = 0; j < c; j++) {
        int s = g_epack[off + j];
        const __half2* p = (const __half2*)(g_hf + (size_t)s * 128) + lane * 2;
        __half2 h0 = p[0], h1 = p[1];
        acc.x += __low2float(h0);  acc.y += __high2float(h0);
        acc.z += __low2float(h1);  acc.w += __high2float(h1);
    }
    float w = 1.0f / (float)(c > 0 ? c : 1);
    __half2* d = (__half2*)(g_xagg2 + (size_t)seg * 128 + lane * 4);
    d[0] = __floats2half2_rn(acc.x * w, acc.y * w);
    d[1] = __floats2half2_rn(acc.z * w, acc.w * w);
}

// ---------------- GEMM: out[m,:] = A[m,0:1152] @ Wstack + bias ----------------
// L1 (FOUT=128): A fp16, B fp16 -> 1 mma product; epilogue relu -> g_hf (fp16).
// L2 (FOUT=64):  A fp16, B = Wh + Wl*2^11 -> 2 mma products; epilogue sigmoid -> out.
template <int FOUT, int LAYER>
__global__ void __launch_bounds__(256)
mm_kernel(const float* __restrict__ bias, float* __restrict__ outExt, int M) {
    constexpr int WN = (FOUT == 128) ? 64 : 32;
    constexpr int NFR = WN / 8;
    constexpr int TB = 128;                 // bytes per smem row (64 fp16)
    constexpr int ABYT = 128 * TB;          // 16 KB
    constexpr int BBYT = FOUT * TB;
    constexpr int NB = (LAYER == 1) ? 1 : 2;
    constexpr int STAGE = ABYT + NB * BBYT; // 32 KB both layers
    constexpr int NCHUNK = 18;

    extern __shared__ char smem[];
    const unsigned sbase = smem_u32(smem);

    const __half* wbh = (LAYER == 1) ? g_wb1 : g_wb2h;
    const __half* wbl = g_wb2l;  // L2 only

    const int tid = threadIdx.x;
    const int wid = tid >> 5, lane = tid & 31;
    const int wm = wid & 3, wn = wid >> 2;
    const int g = lane >> 2, t = lane & 3;
    const int m0 = blockIdx.x * 128;

    float acc[2][NFR][4];
    #pragma unroll
    for (int mi = 0; mi < 2; mi++)
        #pragma unroll
        for (int ni = 0; ni < NFR; ni++)
            #pragma unroll
            for (int q = 0; q < 4; q++) acc[mi][ni][q] = 0.f;

    auto load_chunk = [&](int c, int s) {
        const unsigned a0 = sbase + s * STAGE;
        const unsigned b0 = a0 + ABYT;
        // ---- A: 128 rows x 8 x 16B ----
        #pragma unroll
        for (int i = 0; i < 4; i++) {
            int idx = tid + i * 256;
            int row = idx >> 3, t16 = idx & 7;
            const __half* s0;
            size_t go;
            if (c < 16) {
                s0 = (LAYER == 1) ? g_xagg1 : g_xagg2;
                go = (size_t)(m0 + row) * 1024 + c * 64 + t16 * 8;
            } else {
                s0 = (LAYER == 1) ? g_xf : g_hf;
                go = (size_t)(m0 + row) * 128 + (c - 16) * 64 + t16 * 8;
            }
            unsigned d = a0 + row * TB + ((t16 * 16) ^ ((row & 7) * 16));
            cp16(d, s0 + go);
        }
        // ---- B: NB arrays x FOUT rows x 8 x 16B (1024 chunks both layers) ----
        #pragma unroll
        for (int i = 0; i < 4; i++) {
            int idx = tid + i * 256;
            int arr = idx / (FOUT * 8);
            int rem = idx % (FOUT * 8);
            int row = rem >> 3, t16 = rem & 7;
            const __half* s0 = arr ? wbl : wbh;
            size_t go = (size_t)row * 1152 + c * 64 + t16 * 8;
            unsigned d = b0 + arr * BBYT + row * TB + ((t16 * 16) ^ ((row & 7) * 16));
            cp16(d, s0 + go);
        }
    };

    load_chunk(0, 0);
    CP_COMMIT();

    #pragma unroll 1
    for (int c = 0; c < NCHUNK; c++) {
        if (c < NCHUNK - 1) {
            load_chunk(c + 1, (c + 1) & 1);
            CP_COMMIT();
            CP_WAIT(1);
        } else {
            CP_WAIT(0);
        }
        __syncthreads();

        const int s = c & 1;
        const unsigned sA  = sbase + s * STAGE;
        const unsigned sBh = sA + ABYT;
        const unsigned sBl = sBh + BBYT;

        #pragma unroll
        for (int ks = 0; ks < 4; ks++) {
            const int kb = ks * 32 + t * 4;
            unsigned ah[2][4], bh[NFR][2], bl[NFR][2];
            #pragma unroll
            for (int mi = 0; mi < 2; mi++) {
                int r0 = wm * 32 + mi * 16 + g;
                int r1 = r0 + 8;
                unsigned o00 = r0 * TB + (kb ^ ((r0 & 7) * 16));
                unsigned o10 = r1 * TB + (kb ^ ((r1 & 7) * 16));
                unsigned o01 = r0 * TB + ((kb + 16) ^ ((r0 & 7) * 16));
                unsigned o11 = r1 * TB + ((kb + 16) ^ ((r1 & 7) * 16));
                ah[mi][0] = lds32(sA + o00); ah[mi][1] = lds32(sA + o10);
                ah[mi][2] = lds32(sA + o01); ah[mi][3] = lds32(sA + o11);
            }
            #pragma unroll
            for (int ni = 0; ni < NFR; ni++) {
                int nr = wn * WN + ni * 8 + g;
                unsigned o0 = nr * TB + (kb ^ ((nr & 7) * 16));
                unsigned o1 = nr * TB + ((kb + 16) ^ ((nr & 7) * 16));
                bh[ni][0] = lds32(sBh + o0); bh[ni][1] = lds32(sBh + o1);
                if (LAYER == 2) {
                    bl[ni][0] = lds32(sBl + o0); bl[ni][1] = lds32(sBl + o1);
                }
            }
            #pragma unroll
            for (int mi = 0; mi < 2; mi++) {
                unsigned as[4];
                if (LAYER == 2) {
                    #pragma unroll
                    for (int q = 0; q < 4; q++) as[q] = h2mul(ah[mi][q], H2_INV2048);
                }
                #pragma unroll
                for (int ni = 0; ni < NFR; ni++) {
                    mma_fp16(acc[mi][ni], ah[mi], bh[ni]);
                    if (LAYER == 2) mma_fp16(acc[mi][ni], as, bl[ni]);
                }
            }
        }
        __syncthreads();
    }

    // -------- epilogue --------
    #pragma unroll
    for (int mi = 0; mi < 2; mi++) {
        int row0 = m0 + wm * 32 + mi * 16 + g;
        #pragma unroll
        for (int ni = 0; ni < NFR; ni++) {
            int col = wn * WN + ni * 8 + 2 * t;
            float b0 = bias[col], b1 = bias[col + 1];
            float v[4] = {acc[mi][ni][0] + b0, acc[mi][ni][1] + b1,
                          acc[mi][ni][2] + b0, acc[mi][ni][3] + b1};
            if (LAYER == 1) {
                #pragma unroll
                for (int q = 0; q < 4; q++) v[q] = fmaxf(v[q], 0.f);
                if (row0 < M)
                    *(__half2*)(g_hf + (size_t)row0 * 128 + col) =
                        __floats2half2_rn(v[0], v[1]);
                if (row0 + 8 < M)
                    *(__half2*)(g_hf + (size_t)(row0 + 8) * 128 + col) =
                        __floats2half2_rn(v[2], v[3]);
            } else {
                #pragma unroll
                for (int q = 0; q < 4; q++) v[q] = 1.0f / (1.0f + expf(-v[q]));
                if (row0 < M)
                    *(float2*)(outExt + (size_t)row0 * FOUT + col) = make_float2(v[0], v[1]);
                if (row0 + 8 < M)
                    *(float2*)(outExt + (size_t)(row0 + 8) * FOUT + col) = make_float2(v[2], v[3]);
            }
        }
    }
}

// ---------------- launch ----------------
extern "C" void kernel_launch(void* const* d_in, const int* in_sizes, int n_in,
                              void* d_out, int out_size) {
    const float* x     = (const float*)d_in[0];
    const void*  ei    = d_in[1];
    const void*  et    = d_in[2];
    const float* W1    = (const float*)d_in[3];
    const float* root1 = (const float*)d_in[4];
    const float* b1    = (const float*)d_in[5];
    const float* W2    = (const float*)d_in[6];
    const float* root2 = (const float*)d_in[7];
    const float* b2    = (const float*)d_in[8];
    float* out = (float*)d_out;

    const int M = in_sizes[0] / 128;   // 50000
    const int E = in_sizes[2];         // 500000

    const int SMX = 2 * 32768;         // 64 KB, both layers
    static int configured = 0;
    if (!configured) {
        cudaFuncSetAttribute((const void*)&mm_kernel<128, 1>,
                             cudaFuncAttributeMaxDynamicSharedMemorySize, SMX);
        cudaFuncSetAttribute((const void*)&mm_kernel<64, 2>,
                             cudaFuncAttributeMaxDynamicSharedMemorySize, SMX);
        configured = 1;
    }

    // ---- CSR build ----
    detect_kernel<<<1, 256>>>((const int*)ei);
    int n8 = M * 8;
    zero_kernel<<<(n8 + 255) / 256, 256>>>(n8);
    count_kernel<<<(E + 255) / 256, 256>>>(ei, et, E);
    off_kernel<<<(n8 + 255) / 256, 256>>>(n8);
    fill_kernel<<<(E + 255) / 256, 256>>>(ei, et, E);

    // ---- W pack ----
    int ptot = 128 * 1152 + 64 * 1152;
    pack_kernel<<<(ptot + 255) / 256, 256>>>(W1, root1, W2, root2);

    const int mblocks = (M + 127) / 128;
    const int sblocks = (n8 * 32 + 255) / 256;   // warp per (dst, rel)

    // ---- layer 1 ----
    conv1_kernel<<<(M * 32 + 255) / 256, 256>>>(x, M * 32);
    agg1_kernel<<<sblocks, 256>>>(x, n8);
    mm_kernel<128, 1><<<mblocks, 256, SMX>>>(b1, nullptr, M);

    // ---- layer 2 ----
    agg2_kernel<<<sblocks, 256>>>(n8);
    mm_kernel<64, 2><<<mblocks, 256, SMX>>>(b2, out, M);
}

// round 10
// speedup vs baseline: 2.3007x; 1.0695x over previous
#include <cuda_runtime.h>
#include <cuda_fp16.h>
#include <math.h>

#define NMAX 50048   // 391*128 padded so GEMM tile reads stay in-bounds
#define EMAX 500000

// ---------------- static scratch (no allocations allowed) ----------------
__device__ __half g_xagg1[(size_t)NMAX * 1024];  // L1 per-(dst,rel) mean, fp16
__device__ __half g_xagg2[(size_t)NMAX * 1024];  // L2 per-(dst,rel) mean, fp16
__device__ __half g_xf[(size_t)NMAX * 128];      // L1 root input, fp16
__device__ __half g_hf[(size_t)NMAX * 128];      // relu(h), fp16
__device__ __half g_wb1[128 * 1152];             // L1 stacked W, fp16
__device__ __half g_wb2[64 * 1152];              // L2 stacked W, fp16
__device__ int   g_cnt[NMAX * 8];
__device__ int   g_off8[NMAX * 8];               // start; becomes end after fill
__device__ int   g_epack[EMAX];
__device__ int   g_total;
__device__ int   g_idx64;

// ---------------- helpers ----------------
__device__ __forceinline__ unsigned smem_u32(const void* p) {
    unsigned a;
    asm("{ .reg .u64 t; cvta.to.shared.u64 t, %1; cvt.u32.u64 %0, t; }"
        : "=r"(a) : "l"(p));
    return a;
}
__device__ __forceinline__ unsigned lds32(unsigned a) {
    unsigned v;
    asm volatile("ld.shared.b32 %0, [%1];" : "=r"(v) : "r"(a));
    return v;
}
__device__ __forceinline__ void cp16(unsigned dst, const void* src) {
    asm volatile("cp.async.cg.shared.global [%0], [%1], 16;"
                 :: "r"(dst), "l"(src) : "memory");
}
#define CP_COMMIT() asm volatile("cp.async.commit_group;" ::: "memory")
#define CP_WAIT(n)  asm volatile("cp.async.wait_group %0;" :: "n"(n) : "memory")

__device__ __forceinline__ void mma_fp16(float* c, const unsigned* a, const unsigned* b) {
    asm volatile("mma.sync.aligned.m16n8k16.row.col.f32.f16.f16.f32 "
                 "{%0,%1,%2,%3}, {%4,%5,%6,%7}, {%8,%9}, {%0,%1,%2,%3};"
                 : "+f"(c[0]), "+f"(c[1]), "+f"(c[2]), "+f"(c[3])
                 : "r"(a[0]), "r"(a[1]), "r"(a[2]), "r"(a[3]),
                   "r"(b[0]), "r"(b[1]));
}

__device__ __forceinline__ int load_idx(const void* p, long long i) {
    if (g_idx64) return (int)((const long long*)p)[i];
    return ((const int*)p)[i];
}

// ---------------- launch 1: zero + dtype detect ----------------
__global__ void prep_kernel(const int* __restrict__ ei32, int n8) {
    int i = blockIdx.x * blockDim.x + threadIdx.x;
    if (i < n8) g_cnt[i] = 0;
    if (i == 0) g_total = 0;
    if (blockIdx.x == 0) {
        __shared__ int any;
        if (threadIdx.x == 0) any = 0;
        __syncthreads();
        if (ei32[2 * threadIdx.x + 1] != 0) atomicOr(&any, 1);
        __syncthreads();
        if (threadIdx.x == 0) g_idx64 = (any == 0) ? 1 : 0;
    }
}

// ---------------- launch 2: count ----------------
__global__ void count_kernel(const void* __restrict__ ei,
                             const void* __restrict__ et, int E) {
    int e = blockIdx.x * blockDim.x + threadIdx.x;
    if (e < E) {
        int dst = load_idx(ei, (long long)E + e);
        int r   = load_idx(et, e);
        if ((unsigned)dst < 50000u && (unsigned)r < 8u)
            atomicAdd(&g_cnt[dst * 8 + r], 1);
    }
}

// ---------------- launch 3: offsets (warp-aggregated slot grab) ----------------
__global__ void off_kernel(int n8) {
    int i = blockIdx.x * blockDim.x + threadIdx.x;
    int lane = threadIdx.x & 31;
    int c = (i < n8) ? g_cnt[i] : 0;
    int incl = c;
    #pragma unroll
    for (int d = 1; d < 32; d <<= 1) {
        int t = __shfl_up_sync(0xffffffffu, incl, d);
        if (lane >= d) incl += t;
    }
    int tot = __shfl_sync(0xffffffffu, incl, 31);
    int base = 0;
    if (lane == 0) base = atomicAdd(&g_total, tot);
    base = __shfl_sync(0xffffffffu, base, 0);
    if (i < n8) g_off8[i] = base + incl - c;   // start offset
}

// ---------------- launch 4: fill (atomics directly on g_off8) ----------------
__global__ void fill_kernel(const void* __restrict__ ei,
                            const void* __restrict__ et, int E) {
    int e = blockIdx.x * blockDim.x + threadIdx.x;
    if (e < E) {
        int src = load_idx(ei, e);
        int dst = load_idx(ei, (long long)E + e);
        int r   = load_idx(et, e);
        if ((unsigned)src < 50000u && (unsigned)dst < 50000u && (unsigned)r < 8u) {
            int pos = atomicAdd(&g_off8[dst * 8 + r], 1);
            g_epack[pos] = src;
        }
    }
}
// after fill: g_off8[seg] = start + cnt (end); start = end - cnt

// ---------------- launch 5: mega (agg1 + conv1 + W pack) ----------------
// blocks [0, AGG): warp per (dst,rel) segment — mean of fp32 x rows -> fp16
// blocks [AGG, AGG+CONV): fp32 x -> fp16 g_xf
// blocks [AGG+CONV, ...): stacked W pack (both layers, fp16)
__global__ void __launch_bounds__(256)
mega1_kernel(const float* __restrict__ x,
             const float* __restrict__ W1, const float* __restrict__ root1,
             const float* __restrict__ W2, const float* __restrict__ root2,
             int n8, int M) {
    const int AGG  = (n8 + 7) / 8;            // 8 warps/block, 1 segment/warp
    const int CONV = (M * 32 + 255) / 256;    // float4 per thread
    int b = blockIdx.x;

    if (b < AGG) {
        int seg = b * 8 + (threadIdx.x >> 5);
        int lane = threadIdx.x & 31;
        if (seg >= n8) return;
        int c = g_cnt[seg];
        int off = g_off8[seg] - c;            // start = end - cnt
        float4 acc = make_float4(0.f, 0.f, 0.f, 0.f);
        for (int j = 0; j < c; j++) {
            int s = g_epack[off + j];
            float4 v = ((const float4*)(x + (size_t)s * 128))[lane];
            acc.x += v.x; acc.y += v.y; acc.z += v.z; acc.w += v.w;
        }
        float w = 1.0f / (float)(c > 0 ? c : 1);
        __half2* d = (__half2*)(g_xagg1 + (size_t)seg * 128 + lane * 4);
        d[0] = __floats2half2_rn(acc.x * w, acc.y * w);
        d[1] = __floats2half2_rn(acc.z * w, acc.w * w);
    } else if (b < AGG + CONV) {
        int i = (b - AGG) * 256 + threadIdx.x;
        if (i >= M * 32) return;
        float4 v = ((const float4*)x)[i];
        __half2* d = (__half2*)(g_xf + (size_t)i * 4);
        d[0] = __floats2half2_rn(v.x, v.y);
        d[1] = __floats2half2_rn(v.z, v.w);
    } else {
        int idx = (b - AGG - CONV) * 256 + threadIdx.x;
        const int T1 = 128 * 1152;
        const int T2 = 64 * 1152;
        if (idx < T1) {
            int n = idx / 1152, k = idx % 1152;
            float w = (k < 1024) ? W1[((size_t)(k >> 7) * 128 + (k & 127)) * 128 + n]
                                 : root1[(size_t)(k - 1024) * 128 + n];
            g_wb1[idx] = __float2half_rn(w);
        } else if (idx < T1 + T2) {
            int j = idx - T1;
            int n = j / 1152, k = j % 1152;
            float w = (k < 1024) ? W2[((size_t)(k >> 7) * 128 + (k & 127)) * 64 + n]
                                 : root2[(size_t)(k - 1024) * 64 + n];
            g_wb2[j] = __float2half_rn(w);
        }
    }
}

// ---------------- launch 7: agg2 (mean of fp16 relu(h) rows) ----------------
__global__ void __launch_bounds__(256)
agg2_kernel(int n8) {
    int seg = (blockIdx.x * 256 + threadIdx.x) >> 5;
    int lane = threadIdx.x & 31;
    if (seg >= n8) return;
    int c = g_cnt[seg];
    int off = g_off8[seg] - c;
    float4 acc = make_float4(0.f, 0.f, 0.f, 0.f);
    for (int j = 0; j < c; j++) {
        int s = g_epack[off + j];
        const __half2* p = (const __half2*)(g_hf + (size_t)s * 128) + lane * 2;
        __half2 h0 = p[0], h1 = p[1];
        acc.x += __low2float(h0);  acc.y += __high2float(h0);
        acc.z += __low2float(h1);  acc.w += __high2float(h1);
    }
    float w = 1.0f / (float)(c > 0 ? c : 1);
    __half2* d = (__half2*)(g_xagg2 + (size_t)seg * 128 + lane * 4);
    d[0] = __floats2half2_rn(acc.x * w, acc.y * w);
    d[1] = __floats2half2_rn(acc.z * w, acc.w * w);
}

// ---------------- GEMM: out[m,:] = A[m,0:1152] @ Wstack + bias ----------------
// Single fp16 product both layers. L1 epilogue: relu -> g_hf; L2: sigmoid -> out.
template <int FOUT, int LAYER>
__global__ void __launch_bounds__(256)
mm_kernel(const float* __restrict__ bias, float* __restrict__ outExt, int M) {
    constexpr int WN = (FOUT == 128) ? 64 : 32;
    constexpr int NFR = WN / 8;
    constexpr int TB = 128;                 // bytes per smem row (64 fp16)
    constexpr int ABYT = 128 * TB;          // 16 KB
    constexpr int BBYT = FOUT * TB;         // 16 or 8 KB
    constexpr int STAGE = ABYT + BBYT;
    constexpr int NCHUNK = 18;

    extern __shared__ char smem[];
    const unsigned sbase = smem_u32(smem);

    const __half* wb = (LAYER == 1) ? g_wb1 : g_wb2;

    const int tid = threadIdx.x;
    const int wid = tid >> 5, lane = tid & 31;
    const int wm = wid & 3, wn = wid >> 2;
    const int g = lane >> 2, t = lane & 3;
    const int m0 = blockIdx.x * 128;

    float acc[2][NFR][4];
    #pragma unroll
    for (int mi = 0; mi < 2; mi++)
        #pragma unroll
        for (int ni = 0; ni < NFR; ni++)
            #pragma unroll
            for (int q = 0; q < 4; q++) acc[mi][ni][q] = 0.f;

    auto load_chunk = [&](int c, int s) {
        const unsigned a0 = sbase + s * STAGE;
        const unsigned b0 = a0 + ABYT;
        // ---- A: 128 rows x 8 x 16B ----
        #pragma unroll
        for (int i = 0; i < 4; i++) {
            int idx = tid + i * 256;
            int row = idx >> 3, t16 = idx & 7;
            const __half* s0;
            size_t go;
            if (c < 16) {
                s0 = (LAYER == 1) ? g_xagg1 : g_xagg2;
                go = (size_t)(m0 + row) * 1024 + c * 64 + t16 * 8;
            } else {
                s0 = (LAYER == 1) ? g_xf : g_hf;
                go = (size_t)(m0 + row) * 128 + (c - 16) * 64 + t16 * 8;
            }
            unsigned d = a0 + row * TB + ((t16 * 16) ^ ((row & 7) * 16));
            cp16(d, s0 + go);
        }
        // ---- B: FOUT rows x 8 x 16B ----
        #pragma unroll
        for (int i = 0; i < FOUT / 32; i++) {
            int idx = tid + i * 256;
            int row = idx >> 3, t16 = idx & 7;
            size_t go = (size_t)row * 1152 + c * 64 + t16 * 8;
            unsigned d = b0 + row * TB + ((t16 * 16) ^ ((row & 7) * 16));
            cp16(d, wb + go);
        }
    };

    load_chunk(0, 0);
    CP_COMMIT();

    #pragma unroll 1
    for (int c = 0; c < NCHUNK; c++) {
        if (c < NCHUNK - 1) {
            load_chunk(c + 1, (c + 1) & 1);
            CP_COMMIT();
            CP_WAIT(1);
        } else {
            CP_WAIT(0);
        }
        __syncthreads();

        const int s = c & 1;
        const unsigned sA = sbase + s * STAGE;
        const unsigned sB = sA + ABYT;

        #pragma unroll
        for (int ks = 0; ks < 4; ks++) {
            const int kb = ks * 32 + t * 4;
            unsigned ah[2][4], bh[NFR][2];
            #pragma unroll
            for (int mi = 0; mi < 2; mi++) {
                int r0 = wm * 32 + mi * 16 + g;
                int r1 = r0 + 8;
                unsigned o00 = r0 * TB + (kb ^ ((r0 & 7) * 16));
                unsigned o10 = r1 * TB + (kb ^ ((r1 & 7) * 16));
                unsigned o01 = r0 * TB + ((kb + 16) ^ ((r0 & 7) * 16));
                unsigned o11 = r1 * TB + ((kb + 16) ^ ((r1 & 7) * 16));
                ah[mi][0] = lds32(sA + o00); ah[mi][1] = lds32(sA + o10);
                ah[mi][2] = lds32(sA + o01); ah[mi][3] = lds32(sA + o11);
            }
            #pragma unroll
            for (int ni = 0; ni < NFR; ni++) {
                int nr = wn * WN + ni * 8 + g;
                unsigned o0 = nr * TB + (kb ^ ((nr & 7) * 16));
                unsigned o1 = nr * TB + ((kb + 16) ^ ((nr & 7) * 16));
                bh[ni][0] = lds32(sB + o0); bh[ni][1] = lds32(sB + o1);
            }
            #pragma unroll
            for (int mi = 0; mi < 2; mi++)
                #pragma unroll
                for (int ni = 0; ni < NFR; ni++)
                    mma_fp16(acc[mi][ni], ah[mi], bh[ni]);
        }
        __syncthreads();
    }

    // -------- epilogue --------
    #pragma unroll
    for (int mi = 0; mi < 2; mi++) {
        int row0 = m0 + wm * 32 + mi * 16 + g;
        #pragma unroll
        for (int ni = 0; ni < NFR; ni++) {
            int col = wn * WN + ni * 8 + 2 * t;
            float b0 = bias[col], b1 = bias[col + 1];
            float v[4] = {acc[mi][ni][0] + b0, acc[mi][ni][1] + b1,
                          acc[mi][ni][2] + b0, acc[mi][ni][3] + b1};
            if (LAYER == 1) {
                #pragma unroll
                for (int q = 0; q < 4; q++) v[q] = fmaxf(v[q], 0.f);
                if (row0 < M)
                    *(__half2*)(g_hf + (size_t)row0 * 128 + col) =
                        __floats2half2_rn(v[0], v[1]);
                if (row0 + 8 < M)
                    *(__half2*)(g_hf + (size_t)(row0 + 8) * 128 + col) =
                        __floats2half2_rn(v[2], v[3]);
            } else {
                #pragma unroll
                for (int q = 0; q < 4; q++) v[q] = 1.0f / (1.0f + expf(-v[q]));
                if (row0 < M)
                    *(float2*)(outExt + (size_t)row0 * FOUT + col) = make_float2(v[0], v[1]);
                if (row0 + 8 < M)
                    *(float2*)(outExt + (size_t)(row0 + 8) * FOUT + col) = make_float2(v[2], v[3]);
            }
        }
    }
}

// ---------------- launch ----------------
extern "C" void kernel_launch(void* const* d_in, const int* in_sizes, int n_in,
                              void* d_out, int out_size) {
    const float* x     = (const float*)d_in[0];
    const void*  ei    = d_in[1];
    const void*  et    = d_in[2];
    const float* W1    = (const float*)d_in[3];
    const float* root1 = (const float*)d_in[4];
    const float* b1    = (const float*)d_in[5];
    const float* W2    = (const float*)d_in[6];
    const float* root2 = (const float*)d_in[7];
    const float* b2    = (const float*)d_in[8];
    float* out = (float*)d_out;

    const int M = in_sizes[0] / 128;   // 50000
    const int E = in_sizes[2];         // 500000
    const int n8 = M * 8;

    const int SM1 = 2 * (16384 + 16384);  // 64 KB
    const int SM2 = 2 * (16384 + 8192);   // 48 KB
    static int configured = 0;
    if (!configured) {
        cudaFuncSetAttribute((const void*)&mm_kernel<128, 1>,
                             cudaFuncAttributeMaxDynamicSharedMemorySize, SM1);
        cudaFuncSetAttribute((const void*)&mm_kernel<64, 2>,
                             cudaFuncAttributeMaxDynamicSharedMemorySize, SM2);
        configured = 1;
    }

    // ---- CSR build (4 launches) ----
    prep_kernel<<<(n8 + 255) / 256, 256>>>((const int*)ei, n8);
    count_kernel<<<(E + 255) / 256, 256>>>(ei, et, E);
    off_kernel<<<(n8 + 255) / 256, 256>>>(n8);
    fill_kernel<<<(E + 255) / 256, 256>>>(ei, et, E);

    // ---- mega: agg1 + conv1 + W pack (1 launch) ----
    const int AGG  = (n8 + 7) / 8;
    const int CONV = (M * 32 + 255) / 256;
    const int PACK = (128 * 1152 + 64 * 1152 + 255) / 256;
    mega1_kernel<<<AGG + CONV + PACK, 256>>>(x, W1, root1, W2, root2, n8, M);

    const int mblocks = (M + 127) / 128;

    // ---- layer 1 GEMM ----
    mm_kernel<128, 1><<<mblocks, 256, SM1>>>(b1, nullptr, M);

    // ---- layer 2 ----
    agg2_kernel<<<(n8 * 32 + 255) / 256, 256>>>(n8);
    mm_kernel<64, 2><<<mblocks, 256, SM2>>>(b2, out, M);
}

// round 11
// speedup vs baseline: 2.8254x; 1.2280x over previous
#include <cuda_runtime.h>
#include <cuda_fp16.h>
#include <math.h>

#define NMAX 50048   // 391*128 padded so GEMM tile reads stay in-bounds
#define EMAX 500000

// ---------------- static scratch (no allocations allowed) ----------------
__device__ __half g_xagg1[(size_t)NMAX * 1024];  // L1 per-(dst,rel) mean, fp16
__device__ __half g_xagg2[(size_t)NMAX * 1024];  // L2 per-(dst,rel) mean, fp16
__device__ __half g_xf[(size_t)NMAX * 128];      // L1 root input, fp16
__device__ __half g_hf[(size_t)NMAX * 128];      // relu(h), fp16
__device__ __half g_wb1[128 * 1152];             // L1 stacked W, fp16
__device__ __half g_wb2[64 * 1152];              // L2 stacked W, fp16
__device__ int   g_cnt[NMAX * 8];
__device__ int   g_off8[NMAX * 8];               // start; becomes end after fill
__device__ int   g_epack[EMAX];
__device__ int   g_total;
__device__ int   g_idx64;

// ---------------- helpers ----------------
__device__ __forceinline__ unsigned smem_u32(const void* p) {
    unsigned a;
    asm("{ .reg .u64 t; cvta.to.shared.u64 t, %1; cvt.u32.u64 %0, t; }"
        : "=r"(a) : "l"(p));
    return a;
}
__device__ __forceinline__ unsigned lds32(unsigned a) {
    unsigned v;
    asm volatile("ld.shared.b32 %0, [%1];" : "=r"(v) : "r"(a));
    return v;
}
__device__ __forceinline__ void cp16(unsigned dst, const void* src) {
    asm volatile("cp.async.cg.shared.global [%0], [%1], 16;"
                 :: "r"(dst), "l"(src) : "memory");
}
#define CP_COMMIT() asm volatile("cp.async.commit_group;" ::: "memory")
#define CP_WAIT(n)  asm volatile("cp.async.wait_group %0;" :: "n"(n) : "memory")

__device__ __forceinline__ void mma_fp16(float* c, const unsigned* a, const unsigned* b) {
    asm volatile("mma.sync.aligned.m16n8k16.row.col.f32.f16.f16.f32 "
                 "{%0,%1,%2,%3}, {%4,%5,%6,%7}, {%8,%9}, {%0,%1,%2,%3};"
                 : "+f"(c[0]), "+f"(c[1]), "+f"(c[2]), "+f"(c[3])
                 : "r"(a[0]), "r"(a[1]), "r"(a[2]), "r"(a[3]),
                   "r"(b[0]), "r"(b[1]));
}

__device__ __forceinline__ int load_idx(const void* p, long long i) {
    if (g_idx64) return (int)((const long long*)p)[i];
    return ((const int*)p)[i];
}

// ---------------- launch 1: zero + detect + conv1 + W pack (all independent) --
__global__ void __launch_bounds__(256)
prep_kernel(const int* __restrict__ ei32, const float* __restrict__ x,
            const float* __restrict__ W1, const float* __restrict__ root1,
            const float* __restrict__ W2, const float* __restrict__ root2,
            int n8, int M) {
    const int ZERO = (n8 + 255) / 256;
    const int CONV = (M * 32 + 255) / 256;
    int b = blockIdx.x;

    if (b == 0 && threadIdx.x < 256) {   // dtype detect (block 0 extra duty)
        __shared__ int any;
        if (threadIdx.x == 0) { any = 0; g_total = 0; }
        __syncthreads();
        if (ei32[2 * threadIdx.x + 1] != 0) atomicOr(&any, 1);
        __syncthreads();
        if (threadIdx.x == 0) g_idx64 = (any == 0) ? 1 : 0;
    }

    if (b < ZERO) {
        int i = b * 256 + threadIdx.x;
        if (i < n8) g_cnt[i] = 0;
    } else if (b < ZERO + CONV) {
        int i = (b - ZERO) * 256 + threadIdx.x;
        if (i >= M * 32) return;
        float4 v = ((const float4*)x)[i];
        __half2* d = (__half2*)(g_xf + (size_t)i * 4);
        d[0] = __floats2half2_rn(v.x, v.y);
        d[1] = __floats2half2_rn(v.z, v.w);
    } else {
        int idx = (b - ZERO - CONV) * 256 + threadIdx.x;
        const int T1 = 128 * 1152;
        const int T2 = 64 * 1152;
        if (idx < T1) {
            int n = idx / 1152, k = idx % 1152;
            float w = (k < 1024) ? W1[((size_t)(k >> 7) * 128 + (k & 127)) * 128 + n]
                                 : root1[(size_t)(k - 1024) * 128 + n];
            g_wb1[idx] = __float2half_rn(w);
        } else if (idx < T1 + T2) {
            int j = idx - T1;
            int n = j / 1152, k = j % 1152;
            float w = (k < 1024) ? W2[((size_t)(k >> 7) * 128 + (k & 127)) * 64 + n]
                                 : root2[(size_t)(k - 1024) * 64 + n];
            g_wb2[j] = __float2half_rn(w);
        }
    }
}

// ---------------- launch 2: count ----------------
__global__ void count_kernel(const void* __restrict__ ei,
                             const void* __restrict__ et, int E) {
    int e = blockIdx.x * blockDim.x + threadIdx.x;
    if (e < E) {
        int dst = load_idx(ei, (long long)E + e);
        int r   = load_idx(et, e);
        if ((unsigned)dst < 50000u && (unsigned)r < 8u)
            atomicAdd(&g_cnt[dst * 8 + r], 1);
    }
}

// ---------------- launch 3: offsets (warp-aggregated slot grab) ----------------
__global__ void off_kernel(int n8) {
    int i = blockIdx.x * blockDim.x + threadIdx.x;
    int lane = threadIdx.x & 31;
    int c = (i < n8) ? g_cnt[i] : 0;
    int incl = c;
    #pragma unroll
    for (int d = 1; d < 32; d <<= 1) {
        int t = __shfl_up_sync(0xffffffffu, incl, d);
        if (lane >= d) incl += t;
    }
    int tot = __shfl_sync(0xffffffffu, incl, 31);
    int base = 0;
    if (lane == 0) base = atomicAdd(&g_total, tot);
    base = __shfl_sync(0xffffffffu, base, 0);
    if (i < n8) g_off8[i] = base + incl - c;   // start offset
}

// ---------------- launch 4: fill (atomics directly on g_off8) ----------------
__global__ void fill_kernel(const void* __restrict__ ei,
                            const void* __restrict__ et, int E) {
    int e = blockIdx.x * blockDim.x + threadIdx.x;
    if (e < E) {
        int src = load_idx(ei, e);
        int dst = load_idx(ei, (long long)E + e);
        int r   = load_idx(et, e);
        if ((unsigned)src < 50000u && (unsigned)dst < 50000u && (unsigned)r < 8u) {
            int pos = atomicAdd(&g_off8[dst * 8 + r], 1);
            g_epack[pos] = src;
        }
    }
}
// after fill: g_off8[seg] = start + cnt (end); start = end - cnt

// ---------------- aggregation: HALF-warp (16 lanes) per (dst,rel) segment ------
// fp16 row = 256 B = 16 lanes x uint4 (8 halves each). SRC=0: g_xf, SRC=1: g_hf.
template <int SRC>
__global__ void __launch_bounds__(256)
agg_kernel(int n8) {
    int seg = (blockIdx.x * 256 + threadIdx.x) >> 4;
    int lane = threadIdx.x & 15;
    if (seg >= n8) return;
    int c = g_cnt[seg];
    int off = g_off8[seg] - c;            // start = end - cnt
    const __half* srcp = (SRC == 0) ? g_xf : g_hf;

    float acc[8];
    #pragma unroll
    for (int q = 0; q < 8; q++) acc[q] = 0.f;

    for (int j = 0; j < c; j++) {
        int s = g_epack[off + j];
        uint4 v = ((const uint4*)(srcp + (size_t)s * 128))[lane];
        const __half2* h = (const __half2*)&v;
        #pragma unroll
        for (int q = 0; q < 4; q++) {
            acc[2*q]   += __low2float(h[q]);
            acc[2*q+1] += __high2float(h[q]);
        }
    }
    float w = 1.0f / (float)(c > 0 ? c : 1);
    uint4 o;
    __half2* oh = (__half2*)&o;
    #pragma unroll
    for (int q = 0; q < 4; q++)
        oh[q] = __floats2half2_rn(acc[2*q] * w, acc[2*q+1] * w);
    __half* dstp = (SRC == 0) ? g_xagg1 : g_xagg2;
    ((uint4*)(dstp + (size_t)seg * 128))[lane] = o;
}

// ---------------- GEMM: out[m,:] = A[m,0:1152] @ Wstack + bias ----------------
// Single fp16 product both layers. L1 epilogue: relu -> g_hf; L2: sigmoid -> out.
template <int FOUT, int LAYER>
__global__ void __launch_bounds__(256)
mm_kernel(const float* __restrict__ bias, float* __restrict__ outExt, int M) {
    constexpr int WN = (FOUT == 128) ? 64 : 32;
    constexpr int NFR = WN / 8;
    constexpr int TB = 128;                 // bytes per smem row (64 fp16)
    constexpr int ABYT = 128 * TB;          // 16 KB
    constexpr int BBYT = FOUT * TB;         // 16 or 8 KB
    constexpr int STAGE = ABYT + BBYT;
    constexpr int NCHUNK = 18;

    extern __shared__ char smem[];
    const unsigned sbase = smem_u32(smem);

    const __half* wb = (LAYER == 1) ? g_wb1 : g_wb2;

    const int tid = threadIdx.x;
    const int wid = tid >> 5, lane = tid & 31;
    const int wm = wid & 3, wn = wid >> 2;
    const int g = lane >> 2, t = lane & 3;
    const int m0 = blockIdx.x * 128;

    float acc[2][NFR][4];
    #pragma unroll
    for (int mi = 0; mi < 2; mi++)
        #pragma unroll
        for (int ni = 0; ni < NFR; ni++)
            #pragma unroll
            for (int q = 0; q < 4; q++) acc[mi][ni][q] = 0.f;

    auto load_chunk = [&](int c, int s) {
        const unsigned a0 = sbase + s * STAGE;
        const unsigned b0 = a0 + ABYT;
        // ---- A: 128 rows x 8 x 16B ----
        #pragma unroll
        for (int i = 0; i < 4; i++) {
            int idx = tid + i * 256;
            int row = idx >> 3, t16 = idx & 7;
            const __half* s0;
            size_t go;
            if (c < 16) {
                s0 = (LAYER == 1) ? g_xagg1 : g_xagg2;
                go = (size_t)(m0 + row) * 1024 + c * 64 + t16 * 8;
            } else {
                s0 = (LAYER == 1) ? g_xf : g_hf;
                go = (size_t)(m0 + row) * 128 + (c - 16) * 64 + t16 * 8;
            }
            unsigned d = a0 + row * TB + ((t16 * 16) ^ ((row & 7) * 16));
            cp16(d, s0 + go);
        }
        // ---- B: FOUT rows x 8 x 16B ----
        #pragma unroll
        for (int i = 0; i < FOUT / 32; i++) {
            int idx = tid + i * 256;
            int row = idx >> 3, t16 = idx & 7;
            size_t go = (size_t)row * 1152 + c * 64 + t16 * 8;
            unsigned d = b0 + row * TB + ((t16 * 16) ^ ((row & 7) * 16));
            cp16(d, wb + go);
        }
    };

    load_chunk(0, 0);
    CP_COMMIT();

    #pragma unroll 1
    for (int c = 0; c < NCHUNK; c++) {
        if (c < NCHUNK - 1) {
            load_chunk(c + 1, (c + 1) & 1);
            CP_COMMIT();
            CP_WAIT(1);
        } else {
            CP_WAIT(0);
        }
        __syncthreads();

        const int s = c & 1;
        const unsigned sA = sbase + s * STAGE;
        const unsigned sB = sA + ABYT;

        #pragma unroll
        for (int ks = 0; ks < 4; ks++) {
            const int kb = ks * 32 + t * 4;
            unsigned ah[2][4], bh[NFR][2];
            #pragma unroll
            for (int mi = 0; mi < 2; mi++) {
                int r0 = wm * 32 + mi * 16 + g;
                int r1 = r0 + 8;
                unsigned o00 = r0 * TB + (kb ^ ((r0 & 7) * 16));
                unsigned o10 = r1 * TB + (kb ^ ((r1 & 7) * 16));
                unsigned o01 = r0 * TB + ((kb + 16) ^ ((r0 & 7) * 16));
                unsigned o11 = r1 * TB + ((kb + 16) ^ ((r1 & 7) * 16));
                ah[mi][0] = lds32(sA + o00); ah[mi][1] = lds32(sA + o10);
                ah[mi][2] = lds32(sA + o01); ah[mi][3] = lds32(sA + o11);
            }
            #pragma unroll
            for (int ni = 0; ni < NFR; ni++) {
                int nr = wn * WN + ni * 8 + g;
                unsigned o0 = nr * TB + (kb ^ ((nr & 7) * 16));
                unsigned o1 = nr * TB + ((kb + 16) ^ ((nr & 7) * 16));
                bh[ni][0] = lds32(sB + o0); bh[ni][1] = lds32(sB + o1);
            }
            #pragma unroll
            for (int mi = 0; mi < 2; mi++)
                #pragma unroll
                for (int ni = 0; ni < NFR; ni++)
                    mma_fp16(acc[mi][ni], ah[mi], bh[ni]);
        }
        __syncthreads();
    }

    // -------- epilogue --------
    #pragma unroll
    for (int mi = 0; mi < 2; mi++) {
        int row0 = m0 + wm * 32 + mi * 16 + g;
        #pragma unroll
        for (int ni = 0; ni < NFR; ni++) {
            int col = wn * WN + ni * 8 + 2 * t;
            float b0 = bias[col], b1 = bias[col + 1];
            float v[4] = {acc[mi][ni][0] + b0, acc[mi][ni][1] + b1,
                          acc[mi][ni][2] + b0, acc[mi][ni][3] + b1};
            if (LAYER == 1) {
                #pragma unroll
                for (int q = 0; q < 4; q++) v[q] = fmaxf(v[q], 0.f);
                if (row0 < M)
                    *(__half2*)(g_hf + (size_t)row0 * 128 + col) =
                        __floats2half2_rn(v[0], v[1]);
                if (row0 + 8 < M)
                    *(__half2*)(g_hf + (size_t)(row0 + 8) * 128 + col) =
                        __floats2half2_rn(v[2], v[3]);
            } else {
                #pragma unroll
                for (int q = 0; q < 4; q++) v[q] = 1.0f / (1.0f + expf(-v[q]));
                if (row0 < M)
                    *(float2*)(outExt + (size_t)row0 * FOUT + col) = make_float2(v[0], v[1]);
                if (row0 + 8 < M)
                    *(float2*)(outExt + (size_t)(row0 + 8) * FOUT + col) = make_float2(v[2], v[3]);
            }
        }
    }
}

// ---------------- launch ----------------
extern "C" void kernel_launch(void* const* d_in, const int* in_sizes, int n_in,
                              void* d_out, int out_size) {
    const float* x     = (const float*)d_in[0];
    const void*  ei    = d_in[1];
    const void*  et    = d_in[2];
    const float* W1    = (const float*)d_in[3];
    const float* root1 = (const float*)d_in[4];
    const float* b1    = (const float*)d_in[5];
    const float* W2    = (const float*)d_in[6];
    const float* root2 = (const float*)d_in[7];
    const float* b2    = (const float*)d_in[8];
    float* out = (float*)d_out;

    const int M = in_sizes[0] / 128;   // 50000
    const int E = in_sizes[2];         // 500000
    const int n8 = M * 8;

    const int SM1 = 2 * (16384 + 16384);  // 64 KB
    const int SM2 = 2 * (16384 + 8192);   // 48 KB
    static int configured = 0;
    if (!configured) {
        cudaFuncSetAttribute((const void*)&mm_kernel<128, 1>,
                             cudaFuncAttributeMaxDynamicSharedMemorySize, SM1);
        cudaFuncSetAttribute((const void*)&mm_kernel<64, 2>,
                             cudaFuncAttributeMaxDynamicSharedMemorySize, SM2);
        configured = 1;
    }

    // ---- launch 1: zero + detect + conv1 + W pack ----
    const int ZERO = (n8 + 255) / 256;
    const int CONV = (M * 32 + 255) / 256;
    const int PACK = (128 * 1152 + 64 * 1152 + 255) / 256;
    prep_kernel<<<ZERO + CONV + PACK, 256>>>((const int*)ei, x, W1, root1,
                                             W2, root2, n8, M);

    // ---- CSR build ----
    count_kernel<<<(E + 255) / 256, 256>>>(ei, et, E);
    off_kernel<<<(n8 + 255) / 256, 256>>>(n8);
    fill_kernel<<<(E + 255) / 256, 256>>>(ei, et, E);

    const int mblocks = (M + 127) / 128;
    const int ablocks = (n8 * 16 + 255) / 256;   // half-warp per segment

    // ---- layer 1 ----
    agg_kernel<0><<<ablocks, 256>>>(n8);
    mm_kernel<128, 1><<<mblocks, 256, SM1>>>(b1, nullptr, M);

    // ---- layer 2 ----
    agg_kernel<1><<<ablocks, 256>>>(n8);
    mm_kernel<64, 2><<<mblocks, 256, SM2>>>(b2, out, M);
}

// round 12
// speedup vs baseline: 3.0102x; 1.0654x over previous
#include <cuda_runtime.h>
#include <cuda_fp16.h>
#include <math.h>

#define NMAX 50048   // 391*128 padded so GEMM tile reads stay in-bounds
#define EMAX 500000

// ---------------- static scratch (zero-initialized at load; every replay
// restores g_cnt=0 / g_total=0 at its end, so graph replays are deterministic) --
__device__ __half g_xagg1[(size_t)NMAX * 1024];  // L1 per-(dst,rel) mean, fp16
__device__ __half g_xagg2[(size_t)NMAX * 1024];  // L2 per-(dst,rel) mean, fp16
__device__ __half g_xf[(size_t)NMAX * 128];      // L1 root input, fp16
__device__ __half g_hf[(size_t)NMAX * 128];      // relu(h), fp16
__device__ __half g_wb1[128 * 1152];             // L1 stacked W, fp16
__device__ __half g_wb2[64 * 1152];              // L2 stacked W, fp16
__device__ int   g_cnt[NMAX * 8];
__device__ int   g_off8[NMAX * 8];               // start; becomes end after fill
__device__ int   g_epack[EMAX];
__device__ int   g_total;

// ---------------- helpers ----------------
__device__ __forceinline__ unsigned smem_u32(const void* p) {
    unsigned a;
    asm("{ .reg .u64 t; cvta.to.shared.u64 t, %1; cvt.u32.u64 %0, t; }"
        : "=r"(a) : "l"(p));
    return a;
}
__device__ __forceinline__ unsigned lds32(unsigned a) {
    unsigned v;
    asm volatile("ld.shared.b32 %0, [%1];" : "=r"(v) : "r"(a));
    return v;
}
__device__ __forceinline__ void cp16(unsigned dst, const void* src) {
    asm volatile("cp.async.cg.shared.global [%0], [%1], 16;"
                 :: "r"(dst), "l"(src) : "memory");
}
#define CP_COMMIT() asm volatile("cp.async.commit_group;" ::: "memory")
#define CP_WAIT(n)  asm volatile("cp.async.wait_group %0;" :: "n"(n) : "memory")

__device__ __forceinline__ void mma_fp16(float* c, const unsigned* a, const unsigned* b) {
    asm volatile("mma.sync.aligned.m16n8k16.row.col.f32.f16.f16.f32 "
                 "{%0,%1,%2,%3}, {%4,%5,%6,%7}, {%8,%9}, {%0,%1,%2,%3};"
                 : "+f"(c[0]), "+f"(c[1]), "+f"(c[2]), "+f"(c[3])
                 : "r"(a[0]), "r"(a[1]), "r"(a[2]), "r"(a[3]),
                   "r"(b[0]), "r"(b[1]));
}

// block-local index dtype detect: int64 (LE) => odd 32-bit words all zero over
// 256 samples; int32 => some nonzero. Values are node ids < 50000.
__device__ __forceinline__ bool block_detect_idx64(const int* ei32) {
    __shared__ int any;
    if (threadIdx.x == 0) any = 0;
    __syncthreads();
    if (threadIdx.x < 256 && ei32[2 * threadIdx.x + 1] != 0) atomicOr(&any, 1);
    __syncthreads();
    return any == 0;
}

// ---------------- launch 1: count + conv1 + W pack (independent block ranges) --
__global__ void __launch_bounds__(256)
stage1_kernel(const void* __restrict__ ei, const void* __restrict__ et,
              const float* __restrict__ x,
              const float* __restrict__ W1, const float* __restrict__ root1,
              const float* __restrict__ W2, const float* __restrict__ root2,
              int E, int M) {
    const int CNT  = (E + 255) / 256;
    const int CONV = (M * 32 + 255) / 256;
    int b = blockIdx.x;

    if (b < CNT) {
        bool idx64 = block_detect_idx64((const int*)ei);
        int e = b * 256 + threadIdx.x;
        if (e < E) {
            int dst, r;
            if (idx64) {
                dst = (int)((const long long*)ei)[(long long)E + e];
                r   = (int)((const long long*)et)[e];
            } else {
                dst = ((const int*)ei)[E + e];
                r   = ((const int*)et)[e];
            }
            if ((unsigned)dst < 50000u && (unsigned)r < 8u)
                atomicAdd(&g_cnt[dst * 8 + r], 1);
        }
    } else if (b < CNT + CONV) {
        int i = (b - CNT) * 256 + threadIdx.x;
        if (i >= M * 32) return;
        float4 v = ((const float4*)x)[i];
        __half2* d = (__half2*)(g_xf + (size_t)i * 4);
        d[0] = __floats2half2_rn(v.x, v.y);
        d[1] = __floats2half2_rn(v.z, v.w);
    } else {
        int idx = (b - CNT - CONV) * 256 + threadIdx.x;
        const int T1 = 128 * 1152;
        const int T2 = 64 * 1152;
        if (idx < T1) {
            int n = idx / 1152, k = idx % 1152;
            float w = (k < 1024) ? W1[((size_t)(k >> 7) * 128 + (k & 127)) * 128 + n]
                                 : root1[(size_t)(k - 1024) * 128 + n];
            g_wb1[idx] = __float2half_rn(w);
        } else if (idx < T1 + T2) {
            int j = idx - T1;
            int n = j / 1152, k = j % 1152;
            float w = (k < 1024) ? W2[((size_t)(k >> 7) * 128 + (k & 127)) * 64 + n]
                                 : root2[(size_t)(k - 1024) * 64 + n];
            g_wb2[j] = __float2half_rn(w);
        }
    }
}

// ---------------- launch 2: offsets (warp-aggregated slot grab) ----------------
__global__ void off_kernel(int n8) {
    int i = blockIdx.x * blockDim.x + threadIdx.x;
    int lane = threadIdx.x & 31;
    int c = (i < n8) ? g_cnt[i] : 0;
    int incl = c;
    #pragma unroll
    for (int d = 1; d < 32; d <<= 1) {
        int t = __shfl_up_sync(0xffffffffu, incl, d);
        if (lane >= d) incl += t;
    }
    int tot = __shfl_sync(0xffffffffu, incl, 31);
    int base = 0;
    if (lane == 0) base = atomicAdd(&g_total, tot);
    base = __shfl_sync(0xffffffffu, base, 0);
    if (i < n8) g_off8[i] = base + incl - c;   // start offset
}

// ---------------- launch 3: fill (atomics on g_off8) + g_total reset ----------
__global__ void fill_kernel(const void* __restrict__ ei,
                            const void* __restrict__ et, int E) {
    bool idx64 = block_detect_idx64((const int*)ei);
    int e = blockIdx.x * blockDim.x + threadIdx.x;
    if (e == 0) g_total = 0;   // off already consumed it; reset for next replay
    if (e < E) {
        int src, dst, r;
        if (idx64) {
            src = (int)((const long long*)ei)[e];
            dst = (int)((const long long*)ei)[(long long)E + e];
            r   = (int)((const long long*)et)[e];
        } else {
            src = ((const int*)ei)[e];
            dst = ((const int*)ei)[E + e];
            r   = ((const int*)et)[e];
        }
        if ((unsigned)src < 50000u && (unsigned)dst < 50000u && (unsigned)r < 8u) {
            int pos = atomicAdd(&g_off8[dst * 8 + r], 1);
            g_epack[pos] = src;
        }
    }
}
// after fill: g_off8[seg] = start + cnt (end); start = end - cnt

// ---------------- aggregation: 8 lanes per (dst,rel) segment -------------------
// fp16 row = 256 B = 16 uint4; lane l owns uint4[l] and uint4[l+8].
// Edge loop unrolled by 2 => 4 independent loads in flight per lane.
// SRC=0: g_xf -> g_xagg1. SRC=1: g_hf -> g_xagg2 (+ resets g_cnt for next replay).
template <int SRC>
__global__ void __launch_bounds__(256)
agg_kernel(int n8) {
    int seg = (blockIdx.x * 256 + threadIdx.x) >> 3;
    int lane = threadIdx.x & 7;
    if (seg >= n8) return;
    int c = g_cnt[seg];
    int off = g_off8[seg] - c;            // start = end - cnt
    const __half* srcp = (SRC == 0) ? g_xf : g_hf;

    float acc[16];
    #pragma unroll
    for (int q = 0; q < 16; q++) acc[q] = 0.f;

    int j = 0;
    for (; j + 1 < c; j += 2) {
        int s0 = g_epack[off + j];
        int s1 = g_epack[off + j + 1];
        const uint4* r0 = (const uint4*)(srcp + (size_t)s0 * 128);
        const uint4* r1 = (const uint4*)(srcp + (size_t)s1 * 128);
        uint4 va = r0[lane], vb = r0[lane + 8];
        uint4 wa = r1[lane], wb = r1[lane + 8];
        const __half2* ha = (const __half2*)&va;
        const __half2* hb = (const __half2*)&vb;
        const __half2* ka = (const __half2*)&wa;
        const __half2* kb = (const __half2*)&wb;
        #pragma unroll
        for (int q = 0; q < 4; q++) {
            acc[2*q]      += __low2float(ha[q])  + __low2float(ka[q]);
            acc[2*q+1]    += __high2float(ha[q]) + __high2float(ka[q]);
            acc[8+2*q]    += __low2float(hb[q])  + __low2float(kb[q]);
            acc[8+2*q+1]  += __high2float(hb[q]) + __high2float(kb[q]);
        }
    }
    if (j < c) {
        int s0 = g_epack[off + j];
        const uint4* r0 = (const uint4*)(srcp + (size_t)s0 * 128);
        uint4 va = r0[lane], vb = r0[lane + 8];
        const __half2* ha = (const __half2*)&va;
        const __half2* hb = (const __half2*)&vb;
        #pragma unroll
        for (int q = 0; q < 4; q++) {
            acc[2*q]     += __low2float(ha[q]);
            acc[2*q+1]   += __high2float(ha[q]);
            acc[8+2*q]   += __low2float(hb[q]);
            acc[8+2*q+1] += __high2float(hb[q]);
        }
    }
    float w = 1.0f / (float)(c > 0 ? c : 1);
    uint4 oa, ob;
    __half2* pa = (__half2*)&oa;
    __half2* pb = (__half2*)&ob;
    #pragma unroll
    for (int q = 0; q < 4; q++) {
        pa[q] = __floats2half2_rn(acc[2*q] * w, acc[2*q+1] * w);
        pb[q] = __floats2half2_rn(acc[8+2*q] * w, acc[8+2*q+1] * w);
    }
    __half* dstp = (SRC == 0) ? g_xagg1 : g_xagg2;
    ((uint4*)(dstp + (size_t)seg * 128))[lane] = oa;
    ((uint4*)(dstp + (size_t)seg * 128))[lane + 8] = ob;

    if (SRC == 1 && lane == 0) g_cnt[seg] = 0;   // restore for next replay
}

// ---------------- GEMM: out[m,:] = A[m,0:1152] @ Wstack + bias ----------------
// Single fp16 product both layers. L1 epilogue: relu -> g_hf; L2: sigmoid -> out.
template <int FOUT, int LAYER>
__global__ void __launch_bounds__(256)
mm_kernel(const float* __restrict__ bias, float* __restrict__ outExt, int M) {
    constexpr int WN = (FOUT == 128) ? 64 : 32;
    constexpr int NFR = WN / 8;
    constexpr int TB = 128;                 // bytes per smem row (64 fp16)
    constexpr int ABYT = 128 * TB;          // 16 KB
    constexpr int BBYT = FOUT * TB;         // 16 or 8 KB
    constexpr int STAGE = ABYT + BBYT;
    constexpr int NCHUNK = 18;

    extern __shared__ char smem[];
    const unsigned sbase = smem_u32(smem);

    const __half* wb = (LAYER == 1) ? g_wb1 : g_wb2;

    const int tid = threadIdx.x;
    const int wid = tid >> 5, lane = tid & 31;
    const int wm = wid & 3, wn = wid >> 2;
    const int g = lane >> 2, t = lane & 3;
    const int m0 = blockIdx.x * 128;

    float acc[2][NFR][4];
    #pragma unroll
    for (int mi = 0; mi < 2; mi++)
        #pragma unroll
        for (int ni = 0; ni < NFR; ni++)
            #pragma unroll
            for (int q = 0; q < 4; q++) acc[mi][ni][q] = 0.f;

    auto load_chunk = [&](int c, int s) {
        const unsigned a0 = sbase + s * STAGE;
        const unsigned b0 = a0 + ABYT;
        #pragma unroll
        for (int i = 0; i < 4; i++) {
            int idx = tid + i * 256;
            int row = idx >> 3, t16 = idx & 7;
            const __half* s0;
            size_t go;
            if (c < 16) {
                s0 = (LAYER == 1) ? g_xagg1 : g_xagg2;
                go = (size_t)(m0 + row) * 1024 + c * 64 + t16 * 8;
            } else {
                s0 = (LAYER == 1) ? g_xf : g_hf;
                go = (size_t)(m0 + row) * 128 + (c - 16) * 64 + t16 * 8;
            }
            unsigned d = a0 + row * TB + ((t16 * 16) ^ ((row & 7) * 16));
            cp16(d, s0 + go);
        }
        #pragma unroll
        for (int i = 0; i < FOUT / 32; i++) {
            int idx = tid + i * 256;
            int row = idx >> 3, t16 = idx & 7;
            size_t go = (size_t)row * 1152 + c * 64 + t16 * 8;
            unsigned d = b0 + row * TB + ((t16 * 16) ^ ((row & 7) * 16));
            cp16(d, wb + go);
        }
    };

    load_chunk(0, 0);
    CP_COMMIT();

    #pragma unroll 1
    for (int c = 0; c < NCHUNK; c++) {
        if (c < NCHUNK - 1) {
            load_chunk(c + 1, (c + 1) & 1);
            CP_COMMIT();
            CP_WAIT(1);
        } else {
            CP_WAIT(0);
        }
        __syncthreads();

        const int s = c & 1;
        const unsigned sA = sbase + s * STAGE;
        const unsigned sB = sA + ABYT;

        #pragma unroll
        for (int ks = 0; ks < 4; ks++) {
            const int kb = ks * 32 + t * 4;
            unsigned ah[2][4], bh[NFR][2];
            #pragma unroll
            for (int mi = 0; mi < 2; mi++) {
                int r0 = wm * 32 + mi * 16 + g;
                int r1 = r0 + 8;
                unsigned o00 = r0 * TB + (kb ^ ((r0 & 7) * 16));
                unsigned o10 = r1 * TB + (kb ^ ((r1 & 7) * 16));
                unsigned o01 = r0 * TB + ((kb + 16) ^ ((r0 & 7) * 16));
                unsigned o11 = r1 * TB + ((kb + 16) ^ ((r1 & 7) * 16));
                ah[mi][0] = lds32(sA + o00); ah[mi][1] = lds32(sA + o10);
                ah[mi][2] = lds32(sA + o01); ah[mi][3] = lds32(sA + o11);
            }
            #pragma unroll
            for (int ni = 0; ni < NFR; ni++) {
                int nr = wn * WN + ni * 8 + g;
                unsigned o0 = nr * TB + (kb ^ ((nr & 7) * 16));
                unsigned o1 = nr * TB + ((kb + 16) ^ ((nr & 7) * 16));
                bh[ni][0] = lds32(sB + o0); bh[ni][1] = lds32(sB + o1);
            }
            #pragma unroll
            for (int mi = 0; mi < 2; mi++)
                #pragma unroll
                for (int ni = 0; ni < NFR; ni++)
                    mma_fp16(acc[mi][ni], ah[mi], bh[ni]);
        }
        __syncthreads();
    }

    // -------- epilogue --------
    #pragma unroll
    for (int mi = 0; mi < 2; mi++) {
        int row0 = m0 + wm * 32 + mi * 16 + g;
        #pragma unroll
        for (int ni = 0; ni < NFR; ni++) {
            int col = wn * WN + ni * 8 + 2 * t;
            float b0 = bias[col], b1 = bias[col + 1];
            float v[4] = {acc[mi][ni][0] + b0, acc[mi][ni][1] + b1,
                          acc[mi][ni][2] + b0, acc[mi][ni][3] + b1};
            if (LAYER == 1) {
                #pragma unroll
                for (int q = 0; q < 4; q++) v[q] = fmaxf(v[q], 0.f);
                if (row0 < M)
                    *(__half2*)(g_hf + (size_t)row0 * 128 + col) =
                        __floats2half2_rn(v[0], v[1]);
                if (row0 + 8 < M)
                    *(__half2*)(g_hf + (size_t)(row0 + 8) * 128 + col) =
                        __floats2half2_rn(v[2], v[3]);
            } else {
                #pragma unroll
                for (int q = 0; q < 4; q++) v[q] = 1.0f / (1.0f + expf(-v[q]));
                if (row0 < M)
                    *(float2*)(outExt + (size_t)row0 * FOUT + col) = make_float2(v[0], v[1]);
                if (row0 + 8 < M)
                    *(float2*)(outExt + (size_t)(row0 + 8) * FOUT + col) = make_float2(v[2], v[3]);
            }
        }
    }
}

// ---------------- launch ----------------
extern "C" void kernel_launch(void* const* d_in, const int* in_sizes, int n_in,
                              void* d_out, int out_size) {
    const float* x     = (const float*)d_in[0];
    const void*  ei    = d_in[1];
    const void*  et    = d_in[2];
    const float* W1    = (const float*)d_in[3];
    const float* root1 = (const float*)d_in[4];
    const float* b1    = (const float*)d_in[5];
    const float* W2    = (const float*)d_in[6];
    const float* root2 = (const float*)d_in[7];
    const float* b2    = (const float*)d_in[8];
    float* out = (float*)d_out;

    const int M = in_sizes[0] / 128;   // 50000
    const int E = in_sizes[2];         // 500000
    const int n8 = M * 8;

    const int SM1 = 2 * (16384 + 16384);  // 64 KB
    const int SM2 = 2 * (16384 + 8192);   // 48 KB
    static int configured = 0;
    if (!configured) {
        cudaFuncSetAttribute((const void*)&mm_kernel<128, 1>,
                             cudaFuncAttributeMaxDynamicSharedMemorySize, SM1);
        cudaFuncSetAttribute((const void*)&mm_kernel<64, 2>,
                             cudaFuncAttributeMaxDynamicSharedMemorySize, SM2);
        configured = 1;
    }

    // ---- launch 1: count + conv1 + W pack ----
    const int CNT  = (E + 255) / 256;
    const int CONV = (M * 32 + 255) / 256;
    const int PACK = (128 * 1152 + 64 * 1152 + 255) / 256;
    stage1_kernel<<<CNT + CONV + PACK, 256>>>(ei, et, x, W1, root1, W2, root2, E, M);

    // ---- CSR offsets + fill ----
    off_kernel<<<(n8 + 255) / 256, 256>>>(n8);
    fill_kernel<<<(E + 255) / 256, 256>>>(ei, et, E);

    const int mblocks = (M + 127) / 128;
    const int ablocks = (n8 * 8 + 255) / 256;   // 8 lanes per segment

    // ---- layer 1 ----
    agg_kernel<0><<<ablocks, 256>>>(n8);
    mm_kernel<128, 1><<<mblocks, 256, SM1>>>(b1, nullptr, M);

    // ---- layer 2 ----
    agg_kernel<1><<<ablocks, 256>>>(n8);
    mm_kernel<64, 2><<<mblocks, 256, SM2>>>(b2, out, M);
}